// round 4
// baseline (speedup 1.0000x reference)
#include <cuda_runtime.h>
#include <math.h>
#include <stdint.h>

#define BB 4
#define SS 4096
#define DD 1024
#define HH 16
#define DH 64
#define BSZ 128
#define NB 32          // buckets actually needed (bucket 32 is discarded by [:, :S])
#define EPSF 1e-4f

// ---------------- scratch (static device globals; no allocation) ----------------
__device__ float g_angles[BB*SS*HH];
__device__ int   g_idx[BB*SS*HH];
__device__ float g_qk[(size_t)BB*SS*DD];
__device__ float g_v [(size_t)BB*SS*DD];
__device__ float g_outs[(size_t)BB*SS*DD];
__device__ float g_ch0[BB*SS*HH];

// ---------------- 1) hash: serial-ascending-K fp32 dot (bit-matches cuBLAS sgemm
// mainloop: single accumulator per output, FFMA chain k=0..1023), IEEE div ----
__global__ void __launch_bounds__(1024) hash_kernel(const float* __restrict__ x,
                                                    const float* __restrict__ Wh) {
    __shared__ float xs[32][257];     // 32 tokens x 256-k chunk (padded)
    __shared__ float hs[32][34];
    int g = threadIdx.x;              // token within group (lane)
    int o = threadIdx.y;              // output 0..31 (warp)
    int tid = o * 32 + g;
    int tok0 = blockIdx.x * 32;
    const float* xbase = x + (size_t)tok0 * DD;
    float acc = 0.f;
    for (int c = 0; c < 4; c++) {
        __syncthreads();
        for (int i = tid; i < 32*64; i += 1024) {       // float4 tile loads
            int r = i >> 6, cc = i & 63;
            float4 v = *(const float4*)(xbase + (size_t)r*DD + c*256 + cc*4);
            float* dst = &xs[r][cc*4];
            dst[0]=v.x; dst[1]=v.y; dst[2]=v.z; dst[3]=v.w;
        }
        __syncthreads();
        const float* w = Wh + (size_t)o*DD + c*256;     // uniform per warp
        #pragma unroll 8
        for (int k = 0; k < 256; k++)
            acc = fmaf(xs[g][k], __ldg(w + k), acc);    // serial chain, k ascending
    }
    hs[g][o] = acc;
    __syncthreads();
    if (o < HH) {
        float h0 = hs[g][2*o], h1 = hs[g][2*o+1];
        g_angles[((size_t)(tok0 + g))*HH + o] = __fdiv_rn(h0, h1 + EPSF);
    }
}

// ---------------- 2) per-(b,h) STABLE bitonic argsort of 4096 keys ----------------
// lexicographic (key, index) comparison => output equals stable argsort
__global__ void __launch_bounds__(1024) sort_kernel() {
    int b = blockIdx.x / HH, h = blockIdx.x % HH;
    __shared__ float key[SS];
    __shared__ int   val[SS];
    int tid = threadIdx.x;
    for (int i = tid; i < SS; i += 1024) {
        key[i] = g_angles[((size_t)b*SS + i)*HH + h];
        val[i] = i;
    }
    __syncthreads();
    for (int k = 2; k <= SS; k <<= 1) {
        for (int j = k >> 1; j > 0; j >>= 1) {
            for (int i = tid; i < SS; i += 1024) {
                int ixj = i ^ j;
                if (ixj > i) {
                    bool up = ((i & k) == 0);
                    float ki = key[i], kj = key[ixj];
                    int   vi = val[i], vj = val[ixj];
                    bool gt = (ki > kj) || (ki == kj && vi > vj);
                    if (gt == up) {
                        key[i] = kj; key[ixj] = ki;
                        val[i] = vj; val[ixj] = vi;
                    }
                }
            }
            __syncthreads();
        }
    }
    for (int i = tid; i < SS; i += 1024)
        g_idx[((size_t)b*SS + i)*HH + h] = val[i];
}

// ---------------- 3) SGEMM fp32: C[M,N] = A[M,K] @ W[N,K]^T + bias ----------------
// BM=BN=64, BK=16, 256 threads, 4x4 per thread
__global__ void __launch_bounds__(256) sgemm_nt(const float* __restrict__ A,
                                                const float* __restrict__ W,
                                                const float* __restrict__ bias,
                                                float* __restrict__ C,
                                                int M, int N, int K) {
    __shared__ float As[16][64];
    __shared__ float Ws[16][64];
    int bm = blockIdx.y * 64, bn = blockIdx.x * 64;
    int tid = threadIdx.x;
    int tr = tid / 16, tc = tid % 16;
    int lr = tid / 4, lk = (tid % 4) * 4;
    float acc[4][4] = {};
    for (int k0 = 0; k0 < K; k0 += 16) {
        float4 a = *(const float4*)(A + (size_t)(bm + lr)*K + k0 + lk);
        float4 w = *(const float4*)(W + (size_t)(bn + lr)*K + k0 + lk);
        As[lk+0][lr]=a.x; As[lk+1][lr]=a.y; As[lk+2][lr]=a.z; As[lk+3][lr]=a.w;
        Ws[lk+0][lr]=w.x; Ws[lk+1][lr]=w.y; Ws[lk+2][lr]=w.z; Ws[lk+3][lr]=w.w;
        __syncthreads();
        #pragma unroll
        for (int kk = 0; kk < 16; kk++) {
            float4 av = *(const float4*)(&As[kk][tr*4]);
            float4 wv = *(const float4*)(&Ws[kk][tc*4]);
            float aa[4] = {av.x,av.y,av.z,av.w};
            float ww[4] = {wv.x,wv.y,wv.z,wv.w};
            #pragma unroll
            for (int i=0;i<4;i++)
                #pragma unroll
                for (int j=0;j<4;j++) acc[i][j] += aa[i]*ww[j];
        }
        __syncthreads();
    }
    #pragma unroll
    for (int i=0;i<4;i++) {
        int row = bm + tr*4 + i;
        #pragma unroll
        for (int j=0;j<4;j++) {
            int col = bn + tc*4 + j;
            C[(size_t)row*N + col] = acc[i][j] + bias[col];
        }
    }
}

// ---------------- 4) bucketed local attention (gather fused, fp32) ----------------
#define KPAD 65
#define VPAD 66
__global__ void __launch_bounds__(256) attn_kernel() {
    extern __shared__ float smem[];
    float* sq = smem;                   // 128 x KPAD
    float* sk = sq + 128*KPAD;          // 256 x KPAD
    float* sv = sk + 256*KPAD;          // 256 x VPAD
    int tid = threadIdx.x;
    int n = blockIdx.x, h = blockIdx.y, b = blockIdx.z;
    int base = n * BSZ;

    // gather-load q tile
    for (int p = tid; p < 128*16; p += 256) {
        int r = p >> 4, l16 = p & 15;
        int tok = base + r;
        int s = g_idx[((size_t)b*SS + tok)*HH + h];
        float4 v4 = *(const float4*)(g_qk + ((size_t)b*SS + s)*DD + h*DH + l16*4);
        float* dst = sq + r*KPAD + l16*4;
        dst[0]=v4.x; dst[1]=v4.y; dst[2]=v4.z; dst[3]=v4.w;
    }
    // gather-load k/v window (wraps mod S)
    for (int p = tid; p < 256*16; p += 256) {
        int r = p >> 4, l16 = p & 15;
        int tok = (base + r) & (SS - 1);
        int s = g_idx[((size_t)b*SS + tok)*HH + h];
        size_t off = ((size_t)b*SS + s)*DD + h*DH + l16*4;
        float4 kv = *(const float4*)(g_qk + off);
        float* dk = sk + r*KPAD + l16*4;
        dk[0]=kv.x; dk[1]=kv.y; dk[2]=kv.z; dk[3]=kv.w;
        float4 vv = *(const float4*)(g_v + off);
        float* dv = sv + r*VPAD + l16*4;
        dv[0]=vv.x; dv[1]=vv.y; dv[2]=vv.z; dv[3]=vv.w;
    }
    __syncthreads();

    int warp = tid >> 5, lane = tid & 31;
    for (int row = warp; row < 128; row += 8) {
        float sc[8];
        #pragma unroll
        for (int sl = 0; sl < 8; sl++) sc[sl] = 0.f;
        const float* qr = sq + row*KPAD;
        #pragma unroll 4
        for (int d = 0; d < 64; d++) {
            float qd = qr[d];
            #pragma unroll
            for (int sl = 0; sl < 8; sl++)
                sc[sl] += qd * sk[(lane + 32*sl)*KPAD + d];
        }
        const float scale = 0.03125f;   // 1/sqrt(1024)
        float mx = -INFINITY;
        #pragma unroll
        for (int sl = 0; sl < 8; sl++) {
            int j = lane + 32*sl;
            sc[sl] = (j == row) ? -INFINITY : sc[sl]*scale;  // self-mask
            mx = fmaxf(mx, sc[sl]);
        }
        #pragma unroll
        for (int o = 16; o; o >>= 1) mx = fmaxf(mx, __shfl_xor_sync(0xffffffffu, mx, o));
        float sum = 0.f;
        #pragma unroll
        for (int sl = 0; sl < 8; sl++) { sc[sl] = expf(sc[sl]-mx); sum += sc[sl]; }
        #pragma unroll
        for (int o = 16; o; o >>= 1) sum += __shfl_xor_sync(0xffffffffu, sum, o);
        float inv = 1.f / sum;

        float accx = 0.f, accy = 0.f;
        #pragma unroll
        for (int sl = 0; sl < 8; sl++) {
            float myp = sc[sl];
            #pragma unroll 8
            for (int l2 = 0; l2 < 32; l2++) {
                float a = __shfl_sync(0xffffffffu, myp, l2);
                const float* vr = sv + (sl*32 + l2)*VPAD + lane*2;
                accx += a * vr[0];
                accy += a * vr[1];
            }
        }
        accx *= inv; accy *= inv;
        int t = base + row;
        size_t ooff = ((size_t)b*SS + t)*DD + h*DH + lane*2;
        g_outs[ooff]   = accx;
        g_outs[ooff+1] = accy;
        if (lane == 0) g_ch0[((size_t)b*SS + t)*HH + h] = accx;   // feature 0 (pre-scatter)
    }
}

// ---------------- 5) feature-0-only inverse scatter ----------------
__global__ void __launch_bounds__(256) scatter_kernel() {
    int i = blockIdx.x*256 + threadIdx.x;        // over B*S*H
    if (i >= BB*SS*HH) return;
    int h = i % HH;
    int b = i / (SS*HH);
    int p = g_idx[i];                            // g_idx[(b*S+t)*H+h]
    g_outs[((size_t)b*SS + p)*DD + h*DH] = g_ch0[i];
}

// ---------------- launch ----------------
extern "C" void kernel_launch(void* const* d_in, const int* in_sizes, int n_in,
                              void* d_out, int out_size) {
    const float* x  = (const float*)d_in[0];
    const float* Wh = (const float*)d_in[1];
    const float* Wq = (const float*)d_in[2];
    const float* bq = (const float*)d_in[3];
    const float* Wv = (const float*)d_in[4];
    const float* bv = (const float*)d_in[5];
    const float* Wo = (const float*)d_in[6];
    const float* bo = (const float*)d_in[7];
    float* out = (float*)d_out;

    float* qkp; cudaGetSymbolAddress((void**)&qkp, g_qk);
    float* vp;  cudaGetSymbolAddress((void**)&vp,  g_v);
    float* osp; cudaGetSymbolAddress((void**)&osp, g_outs);

    const int M = BB*SS;   // 16384

    // 1) hash angles (cuBLAS-order serial fp32)
    hash_kernel<<<M/32, dim3(32,32)>>>(x, Wh);
    // 2) stable argsort per (b,h)
    sort_kernel<<<BB*HH, 1024>>>();
    // 3) projections (fp32)
    dim3 gg(DD/64, M/64);
    sgemm_nt<<<gg, 256>>>(x, Wq, bq, qkp, M, DD, DD);
    sgemm_nt<<<gg, 256>>>(x, Wv, bv, vp,  M, DD, DD);
    // 4) attention
    size_t smem = (size_t)(128*KPAD + 256*KPAD + 256*VPAD) * sizeof(float);
    cudaFuncSetAttribute(attn_kernel, cudaFuncAttributeMaxDynamicSharedMemorySize, (int)smem);
    dim3 ag(NB, HH, BB);
    attn_kernel<<<ag, 256, smem>>>();
    // 5) scatter feature 0
    scatter_kernel<<<(BB*SS*HH + 255)/256, 256>>>();
    // 6) output projection
    sgemm_nt<<<gg, 256>>>(osp, Wo, bo, out, M, DD, DD);
}

// round 5
// speedup vs baseline: 1.1807x; 1.1807x over previous
#include <cuda_runtime.h>
#include <math.h>
#include <stdint.h>

#define BB 4
#define SS 4096
#define DD 1024
#define HH 16
#define DH 64
#define BSZ 128
#define NB 32          // buckets actually needed (bucket 32 is discarded by [:, :S])
#define EPSF 1e-4f

// ---------------- scratch (static device globals; no allocation) ----------------
__device__ float g_angles[BB*SS*HH];
__device__ int   g_idx[BB*SS*HH];
__device__ float g_qk[(size_t)BB*SS*DD];
__device__ float g_v [(size_t)BB*SS*DD];
__device__ float g_outs[(size_t)BB*SS*DD];
__device__ float g_ch0[BB*SS*HH];

__device__ __forceinline__ float tf32r(float x) {
    uint32_t u;
    asm("cvt.rna.tf32.f32 %0, %1;" : "=r"(u) : "f"(x));
    return __uint_as_float(u);
}

// ---------------- 1) hash: serial-ascending-K fp32 dot (matches ref), IEEE div ----
__global__ void __launch_bounds__(1024) hash_kernel(const float* __restrict__ x,
                                                    const float* __restrict__ Wh) {
    __shared__ float xs[32][257];     // 32 tokens x 256-k chunk (padded)
    __shared__ float hs[32][34];
    int g = threadIdx.x;              // token within group (lane)
    int o = threadIdx.y;              // output 0..31 (warp)
    int tid = o * 32 + g;
    int tok0 = blockIdx.x * 32;
    const float* xbase = x + (size_t)tok0 * DD;
    float acc = 0.f;
    for (int c = 0; c < 4; c++) {
        __syncthreads();
        for (int i = tid; i < 32*64; i += 1024) {       // float4 tile loads
            int r = i >> 6, cc = i & 63;
            float4 v = *(const float4*)(xbase + (size_t)r*DD + c*256 + cc*4);
            float* dst = &xs[r][cc*4];
            dst[0]=v.x; dst[1]=v.y; dst[2]=v.z; dst[3]=v.w;
        }
        __syncthreads();
        const float* w = Wh + (size_t)o*DD + c*256;     // uniform per warp
        #pragma unroll 8
        for (int k = 0; k < 256; k++)
            acc = fmaf(xs[g][k], __ldg(w + k), acc);    // serial chain, k ascending
    }
    hs[g][o] = acc;
    __syncthreads();
    if (o < HH) {
        float h0 = hs[g][2*o], h1 = hs[g][2*o+1];
        g_angles[((size_t)(tok0 + g))*HH + o] = __fdiv_rn(h0, h1 + EPSF);
    }
}

// ---------------- 2) per-(b,h) STABLE bitonic argsort of 4096 keys ----------------
__global__ void __launch_bounds__(1024) sort_kernel() {
    int b = blockIdx.x / HH, h = blockIdx.x % HH;
    __shared__ float key[SS];
    __shared__ int   val[SS];
    int tid = threadIdx.x;
    for (int i = tid; i < SS; i += 1024) {
        key[i] = g_angles[((size_t)b*SS + i)*HH + h];
        val[i] = i;
    }
    __syncthreads();
    for (int k = 2; k <= SS; k <<= 1) {
        for (int j = k >> 1; j > 0; j >>= 1) {
            for (int i = tid; i < SS; i += 1024) {
                int ixj = i ^ j;
                if (ixj > i) {
                    bool up = ((i & k) == 0);
                    float ki = key[i], kj = key[ixj];
                    int   vi = val[i], vj = val[ixj];
                    bool gt = (ki > kj) || (ki == kj && vi > vj);
                    if (gt == up) {
                        key[i] = kj; key[ixj] = ki;
                        val[i] = vj; val[ixj] = vi;
                    }
                }
            }
            __syncthreads();
        }
    }
    for (int i = tid; i < SS; i += 1024)
        g_idx[((size_t)b*SS + i)*HH + h] = val[i];
}

// ---------------- 3) TF32 tensor-core GEMM: C[M,N] = A[M,K] @ W[N,K]^T + bias ----
// BM=BN=128, BK=32, 256 threads (8 warps, 4x2), warp tile 32x64, m16n8k8 mma.
#define AST 36   // smem row stride (floats): bank = 4*r + c  -> conflict-free frags

__device__ __forceinline__ void mma_tf32(float4& d,
                                         uint32_t a0, uint32_t a1, uint32_t a2, uint32_t a3,
                                         uint32_t b0, uint32_t b1) {
    asm volatile(
        "mma.sync.aligned.m16n8k8.row.col.f32.tf32.tf32.f32 "
        "{%0,%1,%2,%3},{%4,%5,%6,%7},{%8,%9},{%0,%1,%2,%3};"
        : "+f"(d.x), "+f"(d.y), "+f"(d.z), "+f"(d.w)
        : "r"(a0), "r"(a1), "r"(a2), "r"(a3), "r"(b0), "r"(b1));
}

__global__ void __launch_bounds__(256) gemm_tf32(const float* __restrict__ A,
                                                 const float* __restrict__ W,
                                                 const float* __restrict__ bias,
                                                 float* __restrict__ C,
                                                 int M, int N, int K) {
    extern __shared__ float smem[];
    float* As = smem;                  // [2][128][AST]
    float* Bs = smem + 2*128*AST;      // [2][128][AST]

    int tid  = threadIdx.x;
    int lane = tid & 31, wid = tid >> 5;
    int g = lane >> 2, tg = lane & 3;
    int warp_m = (wid & 3) * 32;       // 0,32,64,96
    int warp_n = (wid >> 2) * 64;      // 0,64
    int bm = blockIdx.y * 128, bn = blockIdx.x * 128;

    int lrow = tid >> 1;               // 0..127  (2 float4 per row, 256 thr -> 128 rows x 2)
    int lc4  = (tid & 1) * 4;          // 0 or 4 -> two float4 per row per iter pair
    // each thread loads 4 float4: rows lrow, lrow (c4 and c4+?) -- use simple scheme:
    // 1024 float4 per tile, thread t handles indices t, t+256, t+512, t+768.

    float4 acc[2][8];
    #pragma unroll
    for (int i = 0; i < 2; i++)
        #pragma unroll
        for (int j = 0; j < 8; j++) acc[i][j] = make_float4(0.f,0.f,0.f,0.f);

    float4 pa[4], pb[4];
    // prologue: load tile 0
    #pragma unroll
    for (int i = 0; i < 4; i++) {
        int idx = tid + i*256;
        int r = idx >> 3, c4 = (idx & 7) * 4;
        pa[i] = *(const float4*)(A + (size_t)(bm + r)*K + c4);
        pb[i] = *(const float4*)(W + (size_t)(bn + r)*K + c4);
    }
    #pragma unroll
    for (int i = 0; i < 4; i++) {
        int idx = tid + i*256;
        int r = idx >> 3, c4 = (idx & 7) * 4;
        float* da = As + r*AST + c4;
        da[0]=tf32r(pa[i].x); da[1]=tf32r(pa[i].y); da[2]=tf32r(pa[i].z); da[3]=tf32r(pa[i].w);
        float* db = Bs + r*AST + c4;
        db[0]=tf32r(pb[i].x); db[1]=tf32r(pb[i].y); db[2]=tf32r(pb[i].z); db[3]=tf32r(pb[i].w);
    }
    __syncthreads();

    int nkt = K / 32;
    for (int kt = 0; kt < nkt; kt++) {
        int cur = kt & 1;
        if (kt + 1 < nkt) {
            int k0 = (kt + 1) * 32;
            #pragma unroll
            for (int i = 0; i < 4; i++) {
                int idx = tid + i*256;
                int r = idx >> 3, c4 = (idx & 7) * 4;
                pa[i] = *(const float4*)(A + (size_t)(bm + r)*K + k0 + c4);
                pb[i] = *(const float4*)(W + (size_t)(bn + r)*K + k0 + c4);
            }
        }
        const float* Ab = As + cur*128*AST;
        const float* Bb = Bs + cur*128*AST;
        #pragma unroll
        for (int ks = 0; ks < 4; ks++) {
            int kc = ks * 8;
            uint32_t a[2][4], b[8][2];
            #pragma unroll
            for (int mt = 0; mt < 2; mt++) {
                int r0 = warp_m + mt*16;
                a[mt][0] = __float_as_uint(Ab[(r0+g  )*AST + kc+tg  ]);
                a[mt][1] = __float_as_uint(Ab[(r0+g+8)*AST + kc+tg  ]);
                a[mt][2] = __float_as_uint(Ab[(r0+g  )*AST + kc+tg+4]);
                a[mt][3] = __float_as_uint(Ab[(r0+g+8)*AST + kc+tg+4]);
            }
            #pragma unroll
            for (int nt = 0; nt < 8; nt++) {
                int n0 = warp_n + nt*8;
                b[nt][0] = __float_as_uint(Bb[(n0+g)*AST + kc+tg  ]);
                b[nt][1] = __float_as_uint(Bb[(n0+g)*AST + kc+tg+4]);
            }
            #pragma unroll
            for (int mt = 0; mt < 2; mt++)
                #pragma unroll
                for (int nt = 0; nt < 8; nt++)
                    mma_tf32(acc[mt][nt], a[mt][0],a[mt][1],a[mt][2],a[mt][3],
                             b[nt][0], b[nt][1]);
        }
        if (kt + 1 < nkt) {
            int nxt = (kt + 1) & 1;
            float* Aw = As + nxt*128*AST;
            float* Bw = Bs + nxt*128*AST;
            #pragma unroll
            for (int i = 0; i < 4; i++) {
                int idx = tid + i*256;
                int r = idx >> 3, c4 = (idx & 7) * 4;
                float* da = Aw + r*AST + c4;
                da[0]=tf32r(pa[i].x); da[1]=tf32r(pa[i].y); da[2]=tf32r(pa[i].z); da[3]=tf32r(pa[i].w);
                float* db = Bw + r*AST + c4;
                db[0]=tf32r(pb[i].x); db[1]=tf32r(pb[i].y); db[2]=tf32r(pb[i].z); db[3]=tf32r(pb[i].w);
            }
            __syncthreads();
        }
    }

    // epilogue: bias + store (float2 per fragment row-pair)
    #pragma unroll
    for (int mt = 0; mt < 2; mt++) {
        int r0 = bm + warp_m + mt*16 + g;
        #pragma unroll
        for (int nt = 0; nt < 8; nt++) {
            int col = bn + warp_n + nt*8 + 2*tg;
            float bx = __ldg(bias + col), by = __ldg(bias + col + 1);
            float2 v0 = make_float2(acc[mt][nt].x + bx, acc[mt][nt].y + by);
            float2 v1 = make_float2(acc[mt][nt].z + bx, acc[mt][nt].w + by);
            *(float2*)(C + (size_t)r0*N + col)       = v0;
            *(float2*)(C + (size_t)(r0+8)*N + col)   = v1;
        }
    }
}

// ---------------- 4) bucketed local attention (gather fused, fp32) ----------------
#define KPAD 65
#define VPAD 66
__global__ void __launch_bounds__(256) attn_kernel() {
    extern __shared__ float smem[];
    float* sq = smem;                   // 128 x KPAD
    float* sk = sq + 128*KPAD;          // 256 x KPAD
    float* sv = sk + 256*KPAD;          // 256 x VPAD
    int tid = threadIdx.x;
    int n = blockIdx.x, h = blockIdx.y, b = blockIdx.z;
    int base = n * BSZ;

    for (int p = tid; p < 128*16; p += 256) {
        int r = p >> 4, l16 = p & 15;
        int tok = base + r;
        int s = g_idx[((size_t)b*SS + tok)*HH + h];
        float4 v4 = *(const float4*)(g_qk + ((size_t)b*SS + s)*DD + h*DH + l16*4);
        float* dst = sq + r*KPAD + l16*4;
        dst[0]=v4.x; dst[1]=v4.y; dst[2]=v4.z; dst[3]=v4.w;
    }
    for (int p = tid; p < 256*16; p += 256) {
        int r = p >> 4, l16 = p & 15;
        int tok = (base + r) & (SS - 1);
        int s = g_idx[((size_t)b*SS + tok)*HH + h];
        size_t off = ((size_t)b*SS + s)*DD + h*DH + l16*4;
        float4 kv = *(const float4*)(g_qk + off);
        float* dk = sk + r*KPAD + l16*4;
        dk[0]=kv.x; dk[1]=kv.y; dk[2]=kv.z; dk[3]=kv.w;
        float4 vv = *(const float4*)(g_v + off);
        float* dv = sv + r*VPAD + l16*4;
        dv[0]=vv.x; dv[1]=vv.y; dv[2]=vv.z; dv[3]=vv.w;
    }
    __syncthreads();

    int warp = tid >> 5, lane = tid & 31;
    for (int row = warp; row < 128; row += 8) {
        float sc[8];
        #pragma unroll
        for (int sl = 0; sl < 8; sl++) sc[sl] = 0.f;
        const float* qr = sq + row*KPAD;
        #pragma unroll 4
        for (int d = 0; d < 64; d++) {
            float qd = qr[d];
            #pragma unroll
            for (int sl = 0; sl < 8; sl++)
                sc[sl] += qd * sk[(lane + 32*sl)*KPAD + d];
        }
        const float scale = 0.03125f;   // 1/sqrt(1024)
        float mx = -INFINITY;
        #pragma unroll
        for (int sl = 0; sl < 8; sl++) {
            int j = lane + 32*sl;
            sc[sl] = (j == row) ? -INFINITY : sc[sl]*scale;  // self-mask
            mx = fmaxf(mx, sc[sl]);
        }
        #pragma unroll
        for (int o = 16; o; o >>= 1) mx = fmaxf(mx, __shfl_xor_sync(0xffffffffu, mx, o));
        float sum = 0.f;
        #pragma unroll
        for (int sl = 0; sl < 8; sl++) { sc[sl] = expf(sc[sl]-mx); sum += sc[sl]; }
        #pragma unroll
        for (int o = 16; o; o >>= 1) sum += __shfl_xor_sync(0xffffffffu, sum, o);
        float inv = 1.f / sum;

        float accx = 0.f, accy = 0.f;
        #pragma unroll
        for (int sl = 0; sl < 8; sl++) {
            float myp = sc[sl];
            #pragma unroll 8
            for (int l2 = 0; l2 < 32; l2++) {
                float a = __shfl_sync(0xffffffffu, myp, l2);
                const float* vr = sv + (sl*32 + l2)*VPAD + lane*2;
                accx += a * vr[0];
                accy += a * vr[1];
            }
        }
        accx *= inv; accy *= inv;
        int t = base + row;
        size_t ooff = ((size_t)b*SS + t)*DD + h*DH + lane*2;
        g_outs[ooff]   = accx;
        g_outs[ooff+1] = accy;
        if (lane == 0) g_ch0[((size_t)b*SS + t)*HH + h] = accx;
    }
}

// ---------------- 5) feature-0-only inverse scatter ----------------
__global__ void __launch_bounds__(256) scatter_kernel() {
    int i = blockIdx.x*256 + threadIdx.x;        // over B*S*H
    if (i >= BB*SS*HH) return;
    int h = i % HH;
    int b = i / (SS*HH);
    int p = g_idx[i];
    g_outs[((size_t)b*SS + p)*DD + h*DH] = g_ch0[i];
}

// ---------------- launch ----------------
extern "C" void kernel_launch(void* const* d_in, const int* in_sizes, int n_in,
                              void* d_out, int out_size) {
    const float* x  = (const float*)d_in[0];
    const float* Wh = (const float*)d_in[1];
    const float* Wq = (const float*)d_in[2];
    const float* bq = (const float*)d_in[3];
    const float* Wv = (const float*)d_in[4];
    const float* bv = (const float*)d_in[5];
    const float* Wo = (const float*)d_in[6];
    const float* bo = (const float*)d_in[7];
    float* out = (float*)d_out;

    float* qkp; cudaGetSymbolAddress((void**)&qkp, g_qk);
    float* vp;  cudaGetSymbolAddress((void**)&vp,  g_v);
    float* osp; cudaGetSymbolAddress((void**)&osp, g_outs);

    const int M = BB*SS;   // 16384

    // 1) hash angles (cuBLAS-order serial fp32)
    hash_kernel<<<M/32, dim3(32,32)>>>(x, Wh);
    // 2) stable argsort per (b,h)
    sort_kernel<<<BB*HH, 1024>>>();
    // 3) projections (tf32 tensor cores, fp32 accumulate)
    size_t gsmem = (size_t)(4*128*AST) * sizeof(float);   // 2 bufs x (A+B)
    cudaFuncSetAttribute(gemm_tf32, cudaFuncAttributeMaxDynamicSharedMemorySize, (int)gsmem);
    dim3 gg(DD/128, M/128);
    gemm_tf32<<<gg, 256, gsmem>>>(x, Wq, bq, qkp, M, DD, DD);
    gemm_tf32<<<gg, 256, gsmem>>>(x, Wv, bv, vp,  M, DD, DD);
    // 4) attention
    size_t smem = (size_t)(128*KPAD + 256*KPAD + 256*VPAD) * sizeof(float);
    cudaFuncSetAttribute(attn_kernel, cudaFuncAttributeMaxDynamicSharedMemorySize, (int)smem);
    dim3 ag(NB, HH, BB);
    attn_kernel<<<ag, 256, smem>>>();
    // 5) scatter feature 0
    scatter_kernel<<<(BB*SS*HH + 255)/256, 256>>>();
    // 6) output projection
    gemm_tf32<<<gg, 256, gsmem>>>(osp, Wo, bo, out, M, DD, DD);
}

// round 6
// speedup vs baseline: 3.2530x; 2.7550x over previous
#include <cuda_runtime.h>
#include <math.h>
#include <stdint.h>

#define BB 4
#define SS 4096
#define DD 1024
#define HH 16
#define DH 64
#define BSZ 128
#define NB 32
#define EPSF 1e-4f

// ---------------- scratch ----------------
__device__ float g_angles[BB*SS*HH];
__device__ int   g_idx[BB*SS*HH];
__device__ float g_qk[(size_t)BB*SS*DD];
__device__ float g_v [(size_t)BB*SS*DD];
__device__ float g_outs[(size_t)BB*SS*DD];
__device__ float g_ch0[BB*SS*HH];

__device__ __forceinline__ float tf32r(float x) {
    uint32_t u;
    asm("cvt.rna.tf32.f32 %0, %1;" : "=r"(u) : "f"(x));
    return __uint_as_float(u);
}

__device__ __forceinline__ void mma_tf32(float4& d,
                                         uint32_t a0, uint32_t a1, uint32_t a2, uint32_t a3,
                                         uint32_t b0, uint32_t b1) {
    asm volatile(
        "mma.sync.aligned.m16n8k8.row.col.f32.tf32.tf32.f32 "
        "{%0,%1,%2,%3},{%4,%5,%6,%7},{%8,%9},{%0,%1,%2,%3};"
        : "+f"(d.x), "+f"(d.y), "+f"(d.z), "+f"(d.w)
        : "r"(a0), "r"(a1), "r"(a2), "r"(a3), "r"(b0), "r"(b1));
}

// ---------------- 1) hash: serial-ascending-K fp32 dot (matches ref), IEEE div ----
__global__ void __launch_bounds__(1024) hash_kernel(const float* __restrict__ x,
                                                    const float* __restrict__ Wh) {
    __shared__ float xs[32][257];
    __shared__ float hs[32][34];
    int g = threadIdx.x;
    int o = threadIdx.y;
    int tid = o * 32 + g;
    int tok0 = blockIdx.x * 32;
    const float* xbase = x + (size_t)tok0 * DD;
    float acc = 0.f;
    for (int c = 0; c < 4; c++) {
        __syncthreads();
        for (int i = tid; i < 32*64; i += 1024) {
            int r = i >> 6, cc = i & 63;
            float4 v = *(const float4*)(xbase + (size_t)r*DD + c*256 + cc*4);
            float* dst = &xs[r][cc*4];
            dst[0]=v.x; dst[1]=v.y; dst[2]=v.z; dst[3]=v.w;
        }
        __syncthreads();
        const float* w = Wh + (size_t)o*DD + c*256;
        #pragma unroll 8
        for (int k = 0; k < 256; k++)
            acc = fmaf(xs[g][k], __ldg(w + k), acc);
    }
    hs[g][o] = acc;
    __syncthreads();
    if (o < HH) {
        float h0 = hs[g][2*o], h1 = hs[g][2*o+1];
        g_angles[((size_t)(tok0 + g))*HH + o] = __fdiv_rn(h0, h1 + EPSF);
    }
}

// ---------------- 2) per-(b,h) STABLE bitonic argsort ----------------
__global__ void __launch_bounds__(1024) sort_kernel() {
    int b = blockIdx.x / HH, h = blockIdx.x % HH;
    __shared__ float key[SS];
    __shared__ int   val[SS];
    int tid = threadIdx.x;
    for (int i = tid; i < SS; i += 1024) {
        key[i] = g_angles[((size_t)b*SS + i)*HH + h];
        val[i] = i;
    }
    __syncthreads();
    for (int k = 2; k <= SS; k <<= 1) {
        for (int j = k >> 1; j > 0; j >>= 1) {
            for (int i = tid; i < SS; i += 1024) {
                int ixj = i ^ j;
                if (ixj > i) {
                    bool up = ((i & k) == 0);
                    float ki = key[i], kj = key[ixj];
                    int   vi = val[i], vj = val[ixj];
                    bool gt = (ki > kj) || (ki == kj && vi > vj);
                    if (gt == up) {
                        key[i] = kj; key[ixj] = ki;
                        val[i] = vj; val[ixj] = vi;
                    }
                }
            }
            __syncthreads();
        }
    }
    for (int i = tid; i < SS; i += 1024)
        g_idx[((size_t)b*SS + i)*HH + h] = val[i];
}

// ---------------- 3) TF32 tensor-core GEMM (unchanged from R5) ----------------
#define AST 36

__global__ void __launch_bounds__(256) gemm_tf32(const float* __restrict__ A,
                                                 const float* __restrict__ W,
                                                 const float* __restrict__ bias,
                                                 float* __restrict__ C,
                                                 int M, int N, int K) {
    extern __shared__ float smem[];
    float* As = smem;
    float* Bs = smem + 2*128*AST;

    int tid  = threadIdx.x;
    int lane = tid & 31, wid = tid >> 5;
    int g = lane >> 2, tg = lane & 3;
    int warp_m = (wid & 3) * 32;
    int warp_n = (wid >> 2) * 64;
    int bm = blockIdx.y * 128, bn = blockIdx.x * 128;

    float4 acc[2][8];
    #pragma unroll
    for (int i = 0; i < 2; i++)
        #pragma unroll
        for (int j = 0; j < 8; j++) acc[i][j] = make_float4(0.f,0.f,0.f,0.f);

    float4 pa[4], pb[4];
    #pragma unroll
    for (int i = 0; i < 4; i++) {
        int idx = tid + i*256;
        int r = idx >> 3, c4 = (idx & 7) * 4;
        pa[i] = *(const float4*)(A + (size_t)(bm + r)*K + c4);
        pb[i] = *(const float4*)(W + (size_t)(bn + r)*K + c4);
    }
    #pragma unroll
    for (int i = 0; i < 4; i++) {
        int idx = tid + i*256;
        int r = idx >> 3, c4 = (idx & 7) * 4;
        float* da = As + r*AST + c4;
        da[0]=tf32r(pa[i].x); da[1]=tf32r(pa[i].y); da[2]=tf32r(pa[i].z); da[3]=tf32r(pa[i].w);
        float* db = Bs + r*AST + c4;
        db[0]=tf32r(pb[i].x); db[1]=tf32r(pb[i].y); db[2]=tf32r(pb[i].z); db[3]=tf32r(pb[i].w);
    }
    __syncthreads();

    int nkt = K / 32;
    for (int kt = 0; kt < nkt; kt++) {
        int cur = kt & 1;
        if (kt + 1 < nkt) {
            int k0 = (kt + 1) * 32;
            #pragma unroll
            for (int i = 0; i < 4; i++) {
                int idx = tid + i*256;
                int r = idx >> 3, c4 = (idx & 7) * 4;
                pa[i] = *(const float4*)(A + (size_t)(bm + r)*K + k0 + c4);
                pb[i] = *(const float4*)(W + (size_t)(bn + r)*K + k0 + c4);
            }
        }
        const float* Ab = As + cur*128*AST;
        const float* Bb = Bs + cur*128*AST;
        #pragma unroll
        for (int ks = 0; ks < 4; ks++) {
            int kc = ks * 8;
            uint32_t a[2][4], b[8][2];
            #pragma unroll
            for (int mt = 0; mt < 2; mt++) {
                int r0 = warp_m + mt*16;
                a[mt][0] = __float_as_uint(Ab[(r0+g  )*AST + kc+tg  ]);
                a[mt][1] = __float_as_uint(Ab[(r0+g+8)*AST + kc+tg  ]);
                a[mt][2] = __float_as_uint(Ab[(r0+g  )*AST + kc+tg+4]);
                a[mt][3] = __float_as_uint(Ab[(r0+g+8)*AST + kc+tg+4]);
            }
            #pragma unroll
            for (int nt = 0; nt < 8; nt++) {
                int n0 = warp_n + nt*8;
                b[nt][0] = __float_as_uint(Bb[(n0+g)*AST + kc+tg  ]);
                b[nt][1] = __float_as_uint(Bb[(n0+g)*AST + kc+tg+4]);
            }
            #pragma unroll
            for (int mt = 0; mt < 2; mt++)
                #pragma unroll
                for (int nt = 0; nt < 8; nt++)
                    mma_tf32(acc[mt][nt], a[mt][0],a[mt][1],a[mt][2],a[mt][3],
                             b[nt][0], b[nt][1]);
        }
        if (kt + 1 < nkt) {
            int nxt = (kt + 1) & 1;
            float* Aw = As + nxt*128*AST;
            float* Bw = Bs + nxt*128*AST;
            #pragma unroll
            for (int i = 0; i < 4; i++) {
                int idx = tid + i*256;
                int r = idx >> 3, c4 = (idx & 7) * 4;
                float* da = Aw + r*AST + c4;
                da[0]=tf32r(pa[i].x); da[1]=tf32r(pa[i].y); da[2]=tf32r(pa[i].z); da[3]=tf32r(pa[i].w);
                float* db = Bw + r*AST + c4;
                db[0]=tf32r(pb[i].x); db[1]=tf32r(pb[i].y); db[2]=tf32r(pb[i].z); db[3]=tf32r(pb[i].w);
            }
            __syncthreads();
        }
    }

    #pragma unroll
    for (int mt = 0; mt < 2; mt++) {
        int r0 = bm + warp_m + mt*16 + g;
        #pragma unroll
        for (int nt = 0; nt < 8; nt++) {
            int col = bn + warp_n + nt*8 + 2*tg;
            float bx = __ldg(bias + col), by = __ldg(bias + col + 1);
            float2 v0 = make_float2(acc[mt][nt].x + bx, acc[mt][nt].y + by);
            float2 v1 = make_float2(acc[mt][nt].z + bx, acc[mt][nt].w + by);
            *(float2*)(C + (size_t)r0*N + col)       = v0;
            *(float2*)(C + (size_t)(r0+8)*N + col)   = v1;
        }
    }
}

// ---------------- 4) attention: tf32 mma scores + fp32 softmax + tf32 mma PV ----
#define SST 260   // scores stride (floats), 260 % 32 == 4 -> conflict-free frags
#define QST 68    // q/k tile stride, 68 % 32 == 4
#define VST 260

__global__ void __launch_bounds__(256) attn_kernel() {
    extern __shared__ float smem[];
    float* sS = smem;                    // 128 x SST (scores/P)
    float* sQ = smem + 128*SST;          // 128 x QST
    float* sK = sQ + 128*QST;            // 128 x QST
    float* sVT = sQ;                     // 64 x VST, reuses Q/K region after scores

    int tid = threadIdx.x;
    int lane = tid & 31, wid = tid >> 5;
    int g = lane >> 2, tg = lane & 3;
    int warp_m  = (wid & 3) * 32;        // scores/PV m
    int warp_nS = (wid >> 2) * 64;       // scores n within 128-half
    int warp_nV = (wid >> 2) * 32;       // PV n (d-dim 64)

    int n = blockIdx.x, h = blockIdx.y, b = blockIdx.z;
    int base = n * BSZ;
    const int* idxp = g_idx + (size_t)b*SS*HH + h;
    const float* qkp = g_qk + (size_t)b*SS*DD + h*DH;
    const float* vp  = g_v  + (size_t)b*SS*DD + h*DH;
    const float scale = 0.03125f;        // 1/sqrt(1024)

    // ---- load Q (tf32) + K half0 ----
    for (int p = tid; p < 128*16; p += 256) {
        int r = p >> 4, c = (p & 15) * 4;
        int s = idxp[(size_t)(base + r)*HH];
        float4 q4 = *(const float4*)(qkp + (size_t)s*DD + c);
        float* dst = sQ + r*QST + c;
        dst[0]=tf32r(q4.x); dst[1]=tf32r(q4.y); dst[2]=tf32r(q4.z); dst[3]=tf32r(q4.w);
    }
    for (int p = tid; p < 128*16; p += 256) {
        int r = p >> 4, c = (p & 15) * 4;
        int s = idxp[(size_t)((base + r) & (SS-1))*HH];
        float4 k4 = *(const float4*)(qkp + (size_t)s*DD + c);
        float* dst = sK + r*QST + c;
        dst[0]=tf32r(k4.x); dst[1]=tf32r(k4.y); dst[2]=tf32r(k4.z); dst[3]=tf32r(k4.w);
    }
    __syncthreads();

    // ---- scores halves ----
    #pragma unroll 1
    for (int hf = 0; hf < 2; hf++) {
        if (hf == 1) {
            __syncthreads();   // all warps done reading sK half0
            for (int p = tid; p < 128*16; p += 256) {
                int r = p >> 4, c = (p & 15) * 4;
                int s = idxp[(size_t)((base + 128 + r) & (SS-1))*HH];
                float4 k4 = *(const float4*)(qkp + (size_t)s*DD + c);
                float* dst = sK + r*QST + c;
                dst[0]=tf32r(k4.x); dst[1]=tf32r(k4.y); dst[2]=tf32r(k4.z); dst[3]=tf32r(k4.w);
            }
            __syncthreads();
        }
        float4 acc[2][8];
        #pragma unroll
        for (int i = 0; i < 2; i++)
            #pragma unroll
            for (int j = 0; j < 8; j++) acc[i][j] = make_float4(0.f,0.f,0.f,0.f);

        #pragma unroll
        for (int ks = 0; ks < 8; ks++) {
            int kc = ks * 8;
            uint32_t a[2][4], bfr[8][2];
            #pragma unroll
            for (int mt = 0; mt < 2; mt++) {
                int r0 = warp_m + mt*16;
                a[mt][0] = __float_as_uint(sQ[(r0+g  )*QST + kc+tg  ]);
                a[mt][1] = __float_as_uint(sQ[(r0+g+8)*QST + kc+tg  ]);
                a[mt][2] = __float_as_uint(sQ[(r0+g  )*QST + kc+tg+4]);
                a[mt][3] = __float_as_uint(sQ[(r0+g+8)*QST + kc+tg+4]);
            }
            #pragma unroll
            for (int nt = 0; nt < 8; nt++) {
                int n0 = warp_nS + nt*8;
                bfr[nt][0] = __float_as_uint(sK[(n0+g)*QST + kc+tg  ]);
                bfr[nt][1] = __float_as_uint(sK[(n0+g)*QST + kc+tg+4]);
            }
            #pragma unroll
            for (int mt = 0; mt < 2; mt++)
                #pragma unroll
                for (int nt = 0; nt < 8; nt++)
                    mma_tf32(acc[mt][nt], a[mt][0],a[mt][1],a[mt][2],a[mt][3],
                             bfr[nt][0], bfr[nt][1]);
        }
        // write scores to sS with scale + self-mask (only hf==0 can have j==i)
        #pragma unroll
        for (int mt = 0; mt < 2; mt++) {
            int i0 = warp_m + mt*16 + g;
            #pragma unroll
            for (int nt = 0; nt < 8; nt++) {
                int j0 = warp_nS + nt*8 + 2*tg;
                float4 c = acc[mt][nt];
                float* p0 = sS + i0*SST + hf*128 + j0;
                float* p1 = p0 + 8*SST;
                if (hf == 0) {
                    p0[0] = (j0   == i0  ) ? -INFINITY : c.x*scale;
                    p0[1] = (j0+1 == i0  ) ? -INFINITY : c.y*scale;
                    p1[0] = (j0   == i0+8) ? -INFINITY : c.z*scale;
                    p1[1] = (j0+1 == i0+8) ? -INFINITY : c.w*scale;
                } else {
                    p0[0] = c.x*scale; p0[1] = c.y*scale;
                    p1[0] = c.z*scale; p1[1] = c.w*scale;
                }
            }
        }
    }
    __syncthreads();

    // ---- V^T gather (reuses Q/K smem) + softmax over sS rows ----
    for (int p = tid; p < 256*16; p += 256) {
        int j = p >> 4, dc = (p & 15) * 4;
        int s = idxp[(size_t)((base + j) & (SS-1))*HH];
        float4 vv = *(const float4*)(vp + (size_t)s*DD + dc);
        sVT[(dc+0)*VST + j] = tf32r(vv.x);
        sVT[(dc+1)*VST + j] = tf32r(vv.y);
        sVT[(dc+2)*VST + j] = tf32r(vv.z);
        sVT[(dc+3)*VST + j] = tf32r(vv.w);
    }
    {
        int row = tid >> 1, hf = tid & 1;
        float* rp = sS + row*SST + hf*128;
        float mx = -INFINITY;
        #pragma unroll 8
        for (int c = 0; c < 32; c++) {
            float4 v = ((float4*)rp)[c];
            mx = fmaxf(mx, fmaxf(fmaxf(v.x,v.y), fmaxf(v.z,v.w)));
        }
        mx = fmaxf(mx, __shfl_xor_sync(0xffffffffu, mx, 1));
        float sum = 0.f;
        #pragma unroll 8
        for (int c = 0; c < 32; c++) {
            float4 v = ((float4*)rp)[c];
            v.x = __expf(v.x - mx); v.y = __expf(v.y - mx);
            v.z = __expf(v.z - mx); v.w = __expf(v.w - mx);
            sum += (v.x + v.y) + (v.z + v.w);
            ((float4*)rp)[c] = v;
        }
        sum += __shfl_xor_sync(0xffffffffu, sum, 1);
        float inv = 1.f / sum;
        #pragma unroll 8
        for (int c = 0; c < 32; c++) {
            float4 v = ((float4*)rp)[c];
            v.x = tf32r(v.x*inv); v.y = tf32r(v.y*inv);
            v.z = tf32r(v.z*inv); v.w = tf32r(v.w*inv);
            ((float4*)rp)[c] = v;
        }
    }
    __syncthreads();

    // ---- PV: out[128x64] = P[128x256] @ V^T ----
    float4 o[2][4];
    #pragma unroll
    for (int i = 0; i < 2; i++)
        #pragma unroll
        for (int j = 0; j < 4; j++) o[i][j] = make_float4(0.f,0.f,0.f,0.f);

    #pragma unroll 4
    for (int ks = 0; ks < 32; ks++) {
        int kc = ks * 8;
        uint32_t a[2][4], bfr[4][2];
        #pragma unroll
        for (int mt = 0; mt < 2; mt++) {
            int r0 = warp_m + mt*16;
            a[mt][0] = __float_as_uint(sS[(r0+g  )*SST + kc+tg  ]);
            a[mt][1] = __float_as_uint(sS[(r0+g+8)*SST + kc+tg  ]);
            a[mt][2] = __float_as_uint(sS[(r0+g  )*SST + kc+tg+4]);
            a[mt][3] = __float_as_uint(sS[(r0+g+8)*SST + kc+tg+4]);
        }
        #pragma unroll
        for (int nt = 0; nt < 4; nt++) {
            int n0 = warp_nV + nt*8;
            bfr[nt][0] = __float_as_uint(sVT[(n0+g)*VST + kc+tg  ]);
            bfr[nt][1] = __float_as_uint(sVT[(n0+g)*VST + kc+tg+4]);
        }
        #pragma unroll
        for (int mt = 0; mt < 2; mt++)
            #pragma unroll
            for (int nt = 0; nt < 4; nt++)
                mma_tf32(o[mt][nt], a[mt][0],a[mt][1],a[mt][2],a[mt][3],
                         bfr[nt][0], bfr[nt][1]);
    }

    // ---- epilogue ----
    float* outp = g_outs + (size_t)b*SS*DD + h*DH;
    #pragma unroll
    for (int mt = 0; mt < 2; mt++) {
        int i0 = warp_m + mt*16 + g;
        int t0 = base + i0;
        #pragma unroll
        for (int nt = 0; nt < 4; nt++) {
            int d0 = warp_nV + nt*8 + 2*tg;
            float4 c = o[mt][nt];
            *(float2*)(outp + (size_t)t0*DD + d0)     = make_float2(c.x, c.y);
            *(float2*)(outp + (size_t)(t0+8)*DD + d0) = make_float2(c.z, c.w);
            if (d0 == 0) {
                g_ch0[((size_t)b*SS + t0  )*HH + h] = c.x;
                g_ch0[((size_t)b*SS + t0+8)*HH + h] = c.z;
            }
        }
    }
}

// ---------------- 5) feature-0-only inverse scatter ----------------
__global__ void __launch_bounds__(256) scatter_kernel() {
    int i = blockIdx.x*256 + threadIdx.x;
    if (i >= BB*SS*HH) return;
    int h = i % HH;
    int b = i / (SS*HH);
    int p = g_idx[i];
    g_outs[((size_t)b*SS + p)*DD + h*DH] = g_ch0[i];
}

// ---------------- launch ----------------
extern "C" void kernel_launch(void* const* d_in, const int* in_sizes, int n_in,
                              void* d_out, int out_size) {
    const float* x  = (const float*)d_in[0];
    const float* Wh = (const float*)d_in[1];
    const float* Wq = (const float*)d_in[2];
    const float* bq = (const float*)d_in[3];
    const float* Wv = (const float*)d_in[4];
    const float* bv = (const float*)d_in[5];
    const float* Wo = (const float*)d_in[6];
    const float* bo = (const float*)d_in[7];
    float* out = (float*)d_out;

    float* qkp; cudaGetSymbolAddress((void**)&qkp, g_qk);
    float* vp;  cudaGetSymbolAddress((void**)&vp,  g_v);
    float* osp; cudaGetSymbolAddress((void**)&osp, g_outs);

    const int M = BB*SS;

    hash_kernel<<<M/32, dim3(32,32)>>>(x, Wh);
    sort_kernel<<<BB*HH, 1024>>>();

    size_t gsmem = (size_t)(4*128*AST) * sizeof(float);
    cudaFuncSetAttribute(gemm_tf32, cudaFuncAttributeMaxDynamicSharedMemorySize, (int)gsmem);
    dim3 gg(DD/128, M/128);
    gemm_tf32<<<gg, 256, gsmem>>>(x, Wq, bq, qkp, M, DD, DD);
    gemm_tf32<<<gg, 256, gsmem>>>(x, Wv, bv, vp,  M, DD, DD);

    size_t asmem = (size_t)(128*SST + 2*128*QST) * sizeof(float);   // 202,752 B
    cudaFuncSetAttribute(attn_kernel, cudaFuncAttributeMaxDynamicSharedMemorySize, (int)asmem);
    dim3 ag(NB, HH, BB);
    attn_kernel<<<ag, 256, asmem>>>();

    scatter_kernel<<<(BB*SS*HH + 255)/256, 256>>>();
    gemm_tf32<<<gg, 256, gsmem>>>(osp, Wo, bo, out, M, DD, DD);
}

// round 7
// speedup vs baseline: 3.4209x; 1.0516x over previous
#include <cuda_runtime.h>
#include <math.h>
#include <stdint.h>

#define BB 4
#define SS 4096
#define DD 1024
#define HH 16
#define DH 64
#define BSZ 128
#define NB 32
#define EPSF 1e-4f

// ---------------- scratch ----------------
__device__ float g_angles[BB*SS*HH];
__device__ int   g_idx[BB*SS*HH];
__device__ float g_qk[(size_t)BB*SS*DD];
__device__ float g_v [(size_t)BB*SS*DD];
__device__ float g_outs[(size_t)BB*SS*DD];
__device__ float g_ch0[BB*SS*HH];

__device__ __forceinline__ float tf32r(float x) {
    uint32_t u;
    asm("cvt.rna.tf32.f32 %0, %1;" : "=r"(u) : "f"(x));
    return __uint_as_float(u);
}
__device__ __forceinline__ uint32_t tf32u(float x) {
    uint32_t u;
    asm("cvt.rna.tf32.f32 %0, %1;" : "=r"(u) : "f"(x));
    return u;
}

__device__ __forceinline__ void mma_tf32(float4& d,
                                         uint32_t a0, uint32_t a1, uint32_t a2, uint32_t a3,
                                         uint32_t b0, uint32_t b1) {
    asm volatile(
        "mma.sync.aligned.m16n8k8.row.col.f32.tf32.tf32.f32 "
        "{%0,%1,%2,%3},{%4,%5,%6,%7},{%8,%9},{%0,%1,%2,%3};"
        : "+f"(d.x), "+f"(d.y), "+f"(d.z), "+f"(d.w)
        : "r"(a0), "r"(a1), "r"(a2), "r"(a3), "r"(b0), "r"(b1));
}

__device__ __forceinline__ void cpa16(uint32_t saddr, const float* g) {
    asm volatile("cp.async.cg.shared.global [%0], [%1], 16;\n" :: "r"(saddr), "l"(g));
}

// ---------------- 1) hash: serial-ascending-K fp32 dot (matches ref), IEEE div ----
__global__ void __launch_bounds__(1024) hash_kernel(const float* __restrict__ x,
                                                    const float* __restrict__ Wh) {
    __shared__ float xs[32][257];
    __shared__ float hs[32][34];
    int g = threadIdx.x;
    int o = threadIdx.y;
    int tid = o * 32 + g;
    int tok0 = blockIdx.x * 32;
    const float* xbase = x + (size_t)tok0 * DD;
    float acc = 0.f;
    for (int c = 0; c < 4; c++) {
        __syncthreads();
        for (int i = tid; i < 32*64; i += 1024) {
            int r = i >> 6, cc = i & 63;
            float4 v = *(const float4*)(xbase + (size_t)r*DD + c*256 + cc*4);
            float* dst = &xs[r][cc*4];
            dst[0]=v.x; dst[1]=v.y; dst[2]=v.z; dst[3]=v.w;
        }
        __syncthreads();
        const float* w = Wh + (size_t)o*DD + c*256;
        #pragma unroll 8
        for (int k = 0; k < 256; k++)
            acc = fmaf(xs[g][k], __ldg(w + k), acc);
    }
    hs[g][o] = acc;
    __syncthreads();
    if (o < HH) {
        float h0 = hs[g][2*o], h1 = hs[g][2*o+1];
        g_angles[((size_t)(tok0 + g))*HH + o] = __fdiv_rn(h0, h1 + EPSF);
    }
}

// ---------------- 2) per-(b,h) STABLE bitonic argsort ----------------
__global__ void __launch_bounds__(1024) sort_kernel() {
    int b = blockIdx.x / HH, h = blockIdx.x % HH;
    __shared__ float key[SS];
    __shared__ int   val[SS];
    int tid = threadIdx.x;
    for (int i = tid; i < SS; i += 1024) {
        key[i] = g_angles[((size_t)b*SS + i)*HH + h];
        val[i] = i;
    }
    __syncthreads();
    for (int k = 2; k <= SS; k <<= 1) {
        for (int j = k >> 1; j > 0; j >>= 1) {
            for (int i = tid; i < SS; i += 1024) {
                int ixj = i ^ j;
                if (ixj > i) {
                    bool up = ((i & k) == 0);
                    float ki = key[i], kj = key[ixj];
                    int   vi = val[i], vj = val[ixj];
                    bool gt = (ki > kj) || (ki == kj && vi > vj);
                    if (gt == up) {
                        key[i] = kj; key[ixj] = ki;
                        val[i] = vj; val[ixj] = vi;
                    }
                }
            }
            __syncthreads();
        }
    }
    for (int i = tid; i < SS; i += 1024)
        g_idx[((size_t)b*SS + i)*HH + h] = val[i];
}

// ---------------- 3) TF32 GEMM v2: 128x256x32 block, 8 warps 64x64, cp.async ----
#define AST 36

__global__ void __launch_bounds__(256) gemm2(const float* __restrict__ A,
                                             const float* __restrict__ W0,
                                             const float* __restrict__ b0,
                                             float* __restrict__ C0,
                                             const float* __restrict__ W1,
                                             const float* __restrict__ b1,
                                             float* __restrict__ C1,
                                             int split, int N, int K) {
    extern __shared__ float smem[];
    float* As = smem;                        // [2][128][AST]
    float* Bs = smem + 2*128*AST;            // [2][256][AST]

    const float* W; const float* bias; float* C;
    int bx = blockIdx.x;
    if (bx < split) { W = W0; bias = b0; C = C0; }
    else            { W = W1; bias = b1; C = C1; bx -= split; }
    int bm = blockIdx.y * 128, bn = bx * 256;

    int tid  = threadIdx.x;
    int lane = tid & 31, wid = tid >> 5;
    int g = lane >> 2, tg = lane & 3;
    int warp_m = (wid & 1) * 64;             // 0,64
    int warp_n = (wid >> 1) * 64;            // 0,64,128,192

    float4 acc[4][8];
    #pragma unroll
    for (int i = 0; i < 4; i++)
        #pragma unroll
        for (int j = 0; j < 8; j++) acc[i][j] = make_float4(0.f,0.f,0.f,0.f);

    // cp.async load of one 32-wide K slab into buffer `buf`
    auto load_tile = [&](int k0, int buf) {
        uint32_t abase = (uint32_t)__cvta_generic_to_shared(As + buf*128*AST);
        uint32_t bbase = (uint32_t)__cvta_generic_to_shared(Bs + buf*256*AST);
        #pragma unroll
        for (int i = 0; i < 4; i++) {
            int idx = tid + i*256;
            int r = idx >> 3, c4 = (idx & 7) * 4;
            cpa16(abase + (r*AST + c4)*4, A + (size_t)(bm + r)*K + k0 + c4);
        }
        #pragma unroll
        for (int i = 0; i < 8; i++) {
            int idx = tid + i*256;
            int r = idx >> 3, c4 = (idx & 7) * 4;
            cpa16(bbase + (r*AST + c4)*4, W + (size_t)(bn + r)*K + k0 + c4);
        }
        asm volatile("cp.async.commit_group;\n");
    };

    load_tile(0, 0);

    int nkt = K / 32;
    for (int kt = 0; kt < nkt; kt++) {
        int cur = kt & 1;
        if (kt + 1 < nkt) {
            load_tile((kt + 1) * 32, (kt + 1) & 1);
            asm volatile("cp.async.wait_group 1;\n");
        } else {
            asm volatile("cp.async.wait_group 0;\n");
        }
        __syncthreads();

        const float* Ab = As + cur*128*AST;
        const float* Bb = Bs + cur*256*AST;
        #pragma unroll
        for (int ks = 0; ks < 4; ks++) {
            int kc = ks * 8;
            uint32_t a[4][4], b[8][2];
            #pragma unroll
            for (int mt = 0; mt < 4; mt++) {
                int r0 = warp_m + mt*16;
                a[mt][0] = tf32u(Ab[(r0+g  )*AST + kc+tg  ]);
                a[mt][1] = tf32u(Ab[(r0+g+8)*AST + kc+tg  ]);
                a[mt][2] = tf32u(Ab[(r0+g  )*AST + kc+tg+4]);
                a[mt][3] = tf32u(Ab[(r0+g+8)*AST + kc+tg+4]);
            }
            #pragma unroll
            for (int nt = 0; nt < 8; nt++) {
                int n0 = warp_n + nt*8;
                b[nt][0] = tf32u(Bb[(n0+g)*AST + kc+tg  ]);
                b[nt][1] = tf32u(Bb[(n0+g)*AST + kc+tg+4]);
            }
            #pragma unroll
            for (int mt = 0; mt < 4; mt++)
                #pragma unroll
                for (int nt = 0; nt < 8; nt++)
                    mma_tf32(acc[mt][nt], a[mt][0],a[mt][1],a[mt][2],a[mt][3],
                             b[nt][0], b[nt][1]);
        }
        __syncthreads();   // gate buffer reuse (cp.async writes 2 iters ahead)
    }

    #pragma unroll
    for (int mt = 0; mt < 4; mt++) {
        int r0 = bm + warp_m + mt*16 + g;
        #pragma unroll
        for (int nt = 0; nt < 8; nt++) {
            int col = bn + warp_n + nt*8 + 2*tg;
            float bx2 = __ldg(bias + col), by = __ldg(bias + col + 1);
            float4 c = acc[mt][nt];
            *(float2*)(C + (size_t)r0*N + col)     = make_float2(c.x + bx2, c.y + by);
            *(float2*)(C + (size_t)(r0+8)*N + col) = make_float2(c.z + bx2, c.w + by);
        }
    }
}

// ---------------- 4) attention: tf32 mma scores + fp32 softmax + tf32 mma PV ----
#define SST 260
#define QST 68
#define VST 260

__global__ void __launch_bounds__(256) attn_kernel() {
    extern __shared__ float smem[];
    float* sS = smem;                    // 128 x SST
    float* sQ = smem + 128*SST;          // 128 x QST
    float* sK = sQ + 128*QST;            // 128 x QST
    float* sVT = sQ;                     // 64 x VST (reuse)

    int tid = threadIdx.x;
    int lane = tid & 31, wid = tid >> 5;
    int g = lane >> 2, tg = lane & 3;
    int warp_m  = (wid & 3) * 32;
    int warp_nS = (wid >> 2) * 64;
    int warp_nV = (wid >> 2) * 32;

    int n = blockIdx.x, h = blockIdx.y, b = blockIdx.z;
    int base = n * BSZ;
    const int* idxp = g_idx + (size_t)b*SS*HH + h;
    const float* qkp = g_qk + (size_t)b*SS*DD + h*DH;
    const float* vp  = g_v  + (size_t)b*SS*DD + h*DH;
    const float scale = 0.03125f;

    for (int p = tid; p < 128*16; p += 256) {
        int r = p >> 4, c = (p & 15) * 4;
        int s = idxp[(size_t)(base + r)*HH];
        float4 q4 = *(const float4*)(qkp + (size_t)s*DD + c);
        float* dst = sQ + r*QST + c;
        dst[0]=tf32r(q4.x); dst[1]=tf32r(q4.y); dst[2]=tf32r(q4.z); dst[3]=tf32r(q4.w);
    }
    for (int p = tid; p < 128*16; p += 256) {
        int r = p >> 4, c = (p & 15) * 4;
        int s = idxp[(size_t)((base + r) & (SS-1))*HH];
        float4 k4 = *(const float4*)(qkp + (size_t)s*DD + c);
        float* dst = sK + r*QST + c;
        dst[0]=tf32r(k4.x); dst[1]=tf32r(k4.y); dst[2]=tf32r(k4.z); dst[3]=tf32r(k4.w);
    }
    __syncthreads();

    #pragma unroll 1
    for (int hf = 0; hf < 2; hf++) {
        if (hf == 1) {
            __syncthreads();
            for (int p = tid; p < 128*16; p += 256) {
                int r = p >> 4, c = (p & 15) * 4;
                int s = idxp[(size_t)((base + 128 + r) & (SS-1))*HH];
                float4 k4 = *(const float4*)(qkp + (size_t)s*DD + c);
                float* dst = sK + r*QST + c;
                dst[0]=tf32r(k4.x); dst[1]=tf32r(k4.y); dst[2]=tf32r(k4.z); dst[3]=tf32r(k4.w);
            }
            __syncthreads();
        }
        float4 acc[2][8];
        #pragma unroll
        for (int i = 0; i < 2; i++)
            #pragma unroll
            for (int j = 0; j < 8; j++) acc[i][j] = make_float4(0.f,0.f,0.f,0.f);

        #pragma unroll
        for (int ks = 0; ks < 8; ks++) {
            int kc = ks * 8;
            uint32_t a[2][4], bfr[8][2];
            #pragma unroll
            for (int mt = 0; mt < 2; mt++) {
                int r0 = warp_m + mt*16;
                a[mt][0] = __float_as_uint(sQ[(r0+g  )*QST + kc+tg  ]);
                a[mt][1] = __float_as_uint(sQ[(r0+g+8)*QST + kc+tg  ]);
                a[mt][2] = __float_as_uint(sQ[(r0+g  )*QST + kc+tg+4]);
                a[mt][3] = __float_as_uint(sQ[(r0+g+8)*QST + kc+tg+4]);
            }
            #pragma unroll
            for (int nt = 0; nt < 8; nt++) {
                int n0 = warp_nS + nt*8;
                bfr[nt][0] = __float_as_uint(sK[(n0+g)*QST + kc+tg  ]);
                bfr[nt][1] = __float_as_uint(sK[(n0+g)*QST + kc+tg+4]);
            }
            #pragma unroll
            for (int mt = 0; mt < 2; mt++)
                #pragma unroll
                for (int nt = 0; nt < 8; nt++)
                    mma_tf32(acc[mt][nt], a[mt][0],a[mt][1],a[mt][2],a[mt][3],
                             bfr[nt][0], bfr[nt][1]);
        }
        #pragma unroll
        for (int mt = 0; mt < 2; mt++) {
            int i0 = warp_m + mt*16 + g;
            #pragma unroll
            for (int nt = 0; nt < 8; nt++) {
                int j0 = warp_nS + nt*8 + 2*tg;
                float4 c = acc[mt][nt];
                float* p0 = sS + i0*SST + hf*128 + j0;
                float* p1 = p0 + 8*SST;
                if (hf == 0) {
                    p0[0] = (j0   == i0  ) ? -INFINITY : c.x*scale;
                    p0[1] = (j0+1 == i0  ) ? -INFINITY : c.y*scale;
                    p1[0] = (j0   == i0+8) ? -INFINITY : c.z*scale;
                    p1[1] = (j0+1 == i0+8) ? -INFINITY : c.w*scale;
                } else {
                    p0[0] = c.x*scale; p0[1] = c.y*scale;
                    p1[0] = c.z*scale; p1[1] = c.w*scale;
                }
            }
        }
    }
    __syncthreads();

    for (int p = tid; p < 256*16; p += 256) {
        int j = p >> 4, dc = (p & 15) * 4;
        int s = idxp[(size_t)((base + j) & (SS-1))*HH];
        float4 vv = *(const float4*)(vp + (size_t)s*DD + dc);
        sVT[(dc+0)*VST + j] = tf32r(vv.x);
        sVT[(dc+1)*VST + j] = tf32r(vv.y);
        sVT[(dc+2)*VST + j] = tf32r(vv.z);
        sVT[(dc+3)*VST + j] = tf32r(vv.w);
    }
    {
        int row = tid >> 1, hf = tid & 1;
        float* rp = sS + row*SST + hf*128;
        float mx = -INFINITY;
        #pragma unroll 8
        for (int c = 0; c < 32; c++) {
            float4 v = ((float4*)rp)[c];
            mx = fmaxf(mx, fmaxf(fmaxf(v.x,v.y), fmaxf(v.z,v.w)));
        }
        mx = fmaxf(mx, __shfl_xor_sync(0xffffffffu, mx, 1));
        float sum = 0.f;
        #pragma unroll 8
        for (int c = 0; c < 32; c++) {
            float4 v = ((float4*)rp)[c];
            v.x = __expf(v.x - mx); v.y = __expf(v.y - mx);
            v.z = __expf(v.z - mx); v.w = __expf(v.w - mx);
            sum += (v.x + v.y) + (v.z + v.w);
            ((float4*)rp)[c] = v;
        }
        sum += __shfl_xor_sync(0xffffffffu, sum, 1);
        float inv = 1.f / sum;
        #pragma unroll 8
        for (int c = 0; c < 32; c++) {
            float4 v = ((float4*)rp)[c];
            v.x = tf32r(v.x*inv); v.y = tf32r(v.y*inv);
            v.z = tf32r(v.z*inv); v.w = tf32r(v.w*inv);
            ((float4*)rp)[c] = v;
        }
    }
    __syncthreads();

    float4 o[2][4];
    #pragma unroll
    for (int i = 0; i < 2; i++)
        #pragma unroll
        for (int j = 0; j < 4; j++) o[i][j] = make_float4(0.f,0.f,0.f,0.f);

    #pragma unroll 4
    for (int ks = 0; ks < 32; ks++) {
        int kc = ks * 8;
        uint32_t a[2][4], bfr[4][2];
        #pragma unroll
        for (int mt = 0; mt < 2; mt++) {
            int r0 = warp_m + mt*16;
            a[mt][0] = __float_as_uint(sS[(r0+g  )*SST + kc+tg  ]);
            a[mt][1] = __float_as_uint(sS[(r0+g+8)*SST + kc+tg  ]);
            a[mt][2] = __float_as_uint(sS[(r0+g  )*SST + kc+tg+4]);
            a[mt][3] = __float_as_uint(sS[(r0+g+8)*SST + kc+tg+4]);
        }
        #pragma unroll
        for (int nt = 0; nt < 4; nt++) {
            int n0 = warp_nV + nt*8;
            bfr[nt][0] = __float_as_uint(sVT[(n0+g)*VST + kc+tg  ]);
            bfr[nt][1] = __float_as_uint(sVT[(n0+g)*VST + kc+tg+4]);
        }
        #pragma unroll
        for (int mt = 0; mt < 2; mt++)
            #pragma unroll
            for (int nt = 0; nt < 4; nt++)
                mma_tf32(o[mt][nt], a[mt][0],a[mt][1],a[mt][2],a[mt][3],
                         bfr[nt][0], bfr[nt][1]);
    }

    float* outp = g_outs + (size_t)b*SS*DD + h*DH;
    #pragma unroll
    for (int mt = 0; mt < 2; mt++) {
        int i0 = warp_m + mt*16 + g;
        int t0 = base + i0;
        #pragma unroll
        for (int nt = 0; nt < 4; nt++) {
            int d0 = warp_nV + nt*8 + 2*tg;
            float4 c = o[mt][nt];
            *(float2*)(outp + (size_t)t0*DD + d0)     = make_float2(c.x, c.y);
            *(float2*)(outp + (size_t)(t0+8)*DD + d0) = make_float2(c.z, c.w);
            if (d0 == 0) {
                g_ch0[((size_t)b*SS + t0  )*HH + h] = c.x;
                g_ch0[((size_t)b*SS + t0+8)*HH + h] = c.z;
            }
        }
    }
}

// ---------------- 5) feature-0-only inverse scatter ----------------
__global__ void __launch_bounds__(256) scatter_kernel() {
    int i = blockIdx.x*256 + threadIdx.x;
    if (i >= BB*SS*HH) return;
    int h = i % HH;
    int b = i / (SS*HH);
    int p = g_idx[i];
    g_outs[((size_t)b*SS + p)*DD + h*DH] = g_ch0[i];
}

// ---------------- launch ----------------
extern "C" void kernel_launch(void* const* d_in, const int* in_sizes, int n_in,
                              void* d_out, int out_size) {
    const float* x  = (const float*)d_in[0];
    const float* Wh = (const float*)d_in[1];
    const float* Wq = (const float*)d_in[2];
    const float* bq = (const float*)d_in[3];
    const float* Wv = (const float*)d_in[4];
    const float* bv = (const float*)d_in[5];
    const float* Wo = (const float*)d_in[6];
    const float* bo = (const float*)d_in[7];
    float* out = (float*)d_out;

    float* qkp; cudaGetSymbolAddress((void**)&qkp, g_qk);
    float* vp;  cudaGetSymbolAddress((void**)&vp,  g_v);
    float* osp; cudaGetSymbolAddress((void**)&osp, g_outs);

    const int M = BB*SS;

    hash_kernel<<<M/32, dim3(32,32)>>>(x, Wh);
    sort_kernel<<<BB*HH, 1024>>>();

    size_t gsmem = (size_t)(2*128*AST + 2*256*AST) * sizeof(float);   // 110,592 B
    cudaFuncSetAttribute(gemm2, cudaFuncAttributeMaxDynamicSharedMemorySize, (int)gsmem);
    // fused Q/V projection: grid.x = 8 (4 n-blocks Wq + 4 n-blocks Wv)
    gemm2<<<dim3(8, M/128), 256, gsmem>>>(x, Wq, bq, qkp, Wv, bv, vp, 4, DD, DD);

    size_t asmem = (size_t)(128*SST + 2*128*QST) * sizeof(float);
    cudaFuncSetAttribute(attn_kernel, cudaFuncAttributeMaxDynamicSharedMemorySize, (int)asmem);
    dim3 ag(NB, HH, BB);
    attn_kernel<<<ag, 256, asmem>>>();

    scatter_kernel<<<(BB*SS*HH + 255)/256, 256>>>();
    gemm2<<<dim3(4, M/128), 256, gsmem>>>(osp, Wo, bo, out, Wo, bo, out, 4, DD, DD);
}

// round 8
// speedup vs baseline: 3.4956x; 1.0218x over previous
#include <cuda_runtime.h>
#include <math.h>
#include <stdint.h>

#define BB 4
#define SS 4096
#define DD 1024
#define HH 16
#define DH 64
#define BSZ 128
#define NB 32
#define EPSF 1e-4f

// ---------------- scratch ----------------
__device__ float g_angles[BB*SS*HH];
__device__ int   g_idx[BB*SS*HH];
__device__ float g_qk[(size_t)BB*SS*DD];
__device__ float g_v [(size_t)BB*SS*DD];
__device__ float g_outs[(size_t)BB*SS*DD];
__device__ float g_ch0[BB*SS*HH];

__device__ __forceinline__ float tf32r(float x) {
    uint32_t u;
    asm("cvt.rna.tf32.f32 %0, %1;" : "=r"(u) : "f"(x));
    return __uint_as_float(u);
}
__device__ __forceinline__ uint32_t tf32u(float x) {
    uint32_t u;
    asm("cvt.rna.tf32.f32 %0, %1;" : "=r"(u) : "f"(x));
    return u;
}

__device__ __forceinline__ void mma_tf32(float4& d,
                                         uint32_t a0, uint32_t a1, uint32_t a2, uint32_t a3,
                                         uint32_t b0, uint32_t b1) {
    asm volatile(
        "mma.sync.aligned.m16n8k8.row.col.f32.tf32.tf32.f32 "
        "{%0,%1,%2,%3},{%4,%5,%6,%7},{%8,%9},{%0,%1,%2,%3};"
        : "+f"(d.x), "+f"(d.y), "+f"(d.z), "+f"(d.w)
        : "r"(a0), "r"(a1), "r"(a2), "r"(a3), "r"(b0), "r"(b1));
}

__device__ __forceinline__ void cpa16(uint32_t saddr, const float* g) {
    asm volatile("cp.async.cg.shared.global [%0], [%1], 16;\n" :: "r"(saddr), "l"(g));
}

// ---------------- 1) hash: serial-ascending-K fp32 dot (matches ref), IEEE div ----
__global__ void __launch_bounds__(1024) hash_kernel(const float* __restrict__ x,
                                                    const float* __restrict__ Wh) {
    __shared__ float xs[32][257];
    __shared__ float hs[32][34];
    int g = threadIdx.x;
    int o = threadIdx.y;
    int tid = o * 32 + g;
    int tok0 = blockIdx.x * 32;
    const float* xbase = x + (size_t)tok0 * DD;
    float acc = 0.f;
    for (int c = 0; c < 4; c++) {
        __syncthreads();
        for (int i = tid; i < 32*64; i += 1024) {
            int r = i >> 6, cc = i & 63;
            float4 v = *(const float4*)(xbase + (size_t)r*DD + c*256 + cc*4);
            float* dst = &xs[r][cc*4];
            dst[0]=v.x; dst[1]=v.y; dst[2]=v.z; dst[3]=v.w;
        }
        __syncthreads();
        const float* w = Wh + (size_t)o*DD + c*256;
        #pragma unroll 8
        for (int k = 0; k < 256; k++)
            acc = fmaf(xs[g][k], __ldg(w + k), acc);
    }
    hs[g][o] = acc;
    __syncthreads();
    if (o < HH) {
        float h0 = hs[g][2*o], h1 = hs[g][2*o+1];
        g_angles[((size_t)(tok0 + g))*HH + o] = __fdiv_rn(h0, h1 + EPSF);
    }
}

// ---------------- 2) per-(b,h) STABLE bitonic argsort ----------------
__global__ void __launch_bounds__(1024) sort_kernel() {
    int b = blockIdx.x / HH, h = blockIdx.x % HH;
    __shared__ float key[SS];
    __shared__ int   val[SS];
    int tid = threadIdx.x;
    for (int i = tid; i < SS; i += 1024) {
        key[i] = g_angles[((size_t)b*SS + i)*HH + h];
        val[i] = i;
    }
    __syncthreads();
    for (int k = 2; k <= SS; k <<= 1) {
        for (int j = k >> 1; j > 0; j >>= 1) {
            for (int i = tid; i < SS; i += 1024) {
                int ixj = i ^ j;
                if (ixj > i) {
                    bool up = ((i & k) == 0);
                    float ki = key[i], kj = key[ixj];
                    int   vi = val[i], vj = val[ixj];
                    bool gt = (ki > kj) || (ki == kj && vi > vj);
                    if (gt == up) {
                        key[i] = kj; key[ixj] = ki;
                        val[i] = vj; val[ixj] = vi;
                    }
                }
            }
            __syncthreads();
        }
    }
    for (int i = tid; i < SS; i += 1024)
        g_idx[((size_t)b*SS + i)*HH + h] = val[i];
}

// ---------------- 3) TF32 GEMM v2: 128x256x32 block, 8 warps 64x64, cp.async ----
#define AST 36

__global__ void __launch_bounds__(256) gemm2(const float* __restrict__ A,
                                             const float* __restrict__ W0,
                                             const float* __restrict__ b0,
                                             float* __restrict__ C0,
                                             const float* __restrict__ W1,
                                             const float* __restrict__ b1,
                                             float* __restrict__ C1,
                                             int split, int N, int K) {
    extern __shared__ float smem[];
    float* As = smem;                        // [2][128][AST]
    float* Bs = smem + 2*128*AST;            // [2][256][AST]

    const float* W; const float* bias; float* C;
    int bx = blockIdx.x;
    if (bx < split) { W = W0; bias = b0; C = C0; }
    else            { W = W1; bias = b1; C = C1; bx -= split; }
    int bm = blockIdx.y * 128, bn = bx * 256;

    int tid  = threadIdx.x;
    int lane = tid & 31, wid = tid >> 5;
    int g = lane >> 2, tg = lane & 3;
    int warp_m = (wid & 1) * 64;
    int warp_n = (wid >> 1) * 64;

    float4 acc[4][8];
    #pragma unroll
    for (int i = 0; i < 4; i++)
        #pragma unroll
        for (int j = 0; j < 8; j++) acc[i][j] = make_float4(0.f,0.f,0.f,0.f);

    auto load_tile = [&](int k0, int buf) {
        uint32_t abase = (uint32_t)__cvta_generic_to_shared(As + buf*128*AST);
        uint32_t bbase = (uint32_t)__cvta_generic_to_shared(Bs + buf*256*AST);
        #pragma unroll
        for (int i = 0; i < 4; i++) {
            int idx = tid + i*256;
            int r = idx >> 3, c4 = (idx & 7) * 4;
            cpa16(abase + (r*AST + c4)*4, A + (size_t)(bm + r)*K + k0 + c4);
        }
        #pragma unroll
        for (int i = 0; i < 8; i++) {
            int idx = tid + i*256;
            int r = idx >> 3, c4 = (idx & 7) * 4;
            cpa16(bbase + (r*AST + c4)*4, W + (size_t)(bn + r)*K + k0 + c4);
        }
        asm volatile("cp.async.commit_group;\n");
    };

    load_tile(0, 0);

    int nkt = K / 32;
    for (int kt = 0; kt < nkt; kt++) {
        int cur = kt & 1;
        if (kt + 1 < nkt) {
            load_tile((kt + 1) * 32, (kt + 1) & 1);
            asm volatile("cp.async.wait_group 1;\n");
        } else {
            asm volatile("cp.async.wait_group 0;\n");
        }
        __syncthreads();

        const float* Ab = As + cur*128*AST;
        const float* Bb = Bs + cur*256*AST;
        #pragma unroll
        for (int ks = 0; ks < 4; ks++) {
            int kc = ks * 8;
            uint32_t a[4][4], b[8][2];
            #pragma unroll
            for (int mt = 0; mt < 4; mt++) {
                int r0 = warp_m + mt*16;
                a[mt][0] = tf32u(Ab[(r0+g  )*AST + kc+tg  ]);
                a[mt][1] = tf32u(Ab[(r0+g+8)*AST + kc+tg  ]);
                a[mt][2] = tf32u(Ab[(r0+g  )*AST + kc+tg+4]);
                a[mt][3] = tf32u(Ab[(r0+g+8)*AST + kc+tg+4]);
            }
            #pragma unroll
            for (int nt = 0; nt < 8; nt++) {
                int n0 = warp_n + nt*8;
                b[nt][0] = tf32u(Bb[(n0+g)*AST + kc+tg  ]);
                b[nt][1] = tf32u(Bb[(n0+g)*AST + kc+tg+4]);
            }
            #pragma unroll
            for (int mt = 0; mt < 4; mt++)
                #pragma unroll
                for (int nt = 0; nt < 8; nt++)
                    mma_tf32(acc[mt][nt], a[mt][0],a[mt][1],a[mt][2],a[mt][3],
                             b[nt][0], b[nt][1]);
        }
        __syncthreads();
    }

    #pragma unroll
    for (int mt = 0; mt < 4; mt++) {
        int r0 = bm + warp_m + mt*16 + g;
        #pragma unroll
        for (int nt = 0; nt < 8; nt++) {
            int col = bn + warp_n + nt*8 + 2*tg;
            float bx2 = __ldg(bias + col), by = __ldg(bias + col + 1);
            float4 c = acc[mt][nt];
            *(float2*)(C + (size_t)r0*N + col)     = make_float2(c.x + bx2, c.y + by);
            *(float2*)(C + (size_t)(r0+8)*N + col) = make_float2(c.z + bx2, c.w + by);
        }
    }
}

// ---------------- 4) attention: 512 threads, 16 warps ----------------
#define SST 260
#define QST 68
#define VST 260

__global__ void __launch_bounds__(512) attn_kernel() {
    extern __shared__ float smem[];
    float* sS = smem;                    // 128 x SST
    float* sQ = smem + 128*SST;          // 128 x QST
    float* sK = sQ + 128*QST;            // 128 x QST
    float* sVT = sQ;                     // 64 x VST (reuse)

    int tid = threadIdx.x;
    int lane = tid & 31, wid = tid >> 5;
    int g = lane >> 2, tg = lane & 3;
    int warp_m  = (wid & 7) * 16;        // 8 m-tiles of 16 rows
    int warp_nS = (wid >> 3) * 64;       // 2 n-halves for scores
    int warp_nV = (wid >> 3) * 32;       // 2 n-halves for PV

    int n = blockIdx.x, h = blockIdx.y, b = blockIdx.z;
    int base = n * BSZ;
    const int* idxp = g_idx + (size_t)b*SS*HH + h;
    const float* qkp = g_qk + (size_t)b*SS*DD + h*DH;
    const float* vp  = g_v  + (size_t)b*SS*DD + h*DH;
    const float scale = 0.03125f;

    for (int p = tid; p < 128*16; p += 512) {
        int r = p >> 4, c = (p & 15) * 4;
        int s = idxp[(size_t)(base + r)*HH];
        float4 q4 = *(const float4*)(qkp + (size_t)s*DD + c);
        float* dst = sQ + r*QST + c;
        dst[0]=tf32r(q4.x); dst[1]=tf32r(q4.y); dst[2]=tf32r(q4.z); dst[3]=tf32r(q4.w);
    }
    for (int p = tid; p < 128*16; p += 512) {
        int r = p >> 4, c = (p & 15) * 4;
        int s = idxp[(size_t)((base + r) & (SS-1))*HH];
        float4 k4 = *(const float4*)(qkp + (size_t)s*DD + c);
        float* dst = sK + r*QST + c;
        dst[0]=tf32r(k4.x); dst[1]=tf32r(k4.y); dst[2]=tf32r(k4.z); dst[3]=tf32r(k4.w);
    }
    __syncthreads();

    #pragma unroll 1
    for (int hf = 0; hf < 2; hf++) {
        if (hf == 1) {
            __syncthreads();
            for (int p = tid; p < 128*16; p += 512) {
                int r = p >> 4, c = (p & 15) * 4;
                int s = idxp[(size_t)((base + 128 + r) & (SS-1))*HH];
                float4 k4 = *(const float4*)(qkp + (size_t)s*DD + c);
                float* dst = sK + r*QST + c;
                dst[0]=tf32r(k4.x); dst[1]=tf32r(k4.y); dst[2]=tf32r(k4.z); dst[3]=tf32r(k4.w);
            }
            __syncthreads();
        }
        float4 acc[8];
        #pragma unroll
        for (int j = 0; j < 8; j++) acc[j] = make_float4(0.f,0.f,0.f,0.f);

        #pragma unroll
        for (int ks = 0; ks < 8; ks++) {
            int kc = ks * 8;
            uint32_t a[4], bfr[8][2];
            a[0] = __float_as_uint(sQ[(warp_m+g  )*QST + kc+tg  ]);
            a[1] = __float_as_uint(sQ[(warp_m+g+8)*QST + kc+tg  ]);
            a[2] = __float_as_uint(sQ[(warp_m+g  )*QST + kc+tg+4]);
            a[3] = __float_as_uint(sQ[(warp_m+g+8)*QST + kc+tg+4]);
            #pragma unroll
            for (int nt = 0; nt < 8; nt++) {
                int n0 = warp_nS + nt*8;
                bfr[nt][0] = __float_as_uint(sK[(n0+g)*QST + kc+tg  ]);
                bfr[nt][1] = __float_as_uint(sK[(n0+g)*QST + kc+tg+4]);
            }
            #pragma unroll
            for (int nt = 0; nt < 8; nt++)
                mma_tf32(acc[nt], a[0],a[1],a[2],a[3], bfr[nt][0], bfr[nt][1]);
        }
        {
            int i0 = warp_m + g;
            #pragma unroll
            for (int nt = 0; nt < 8; nt++) {
                int j0 = warp_nS + nt*8 + 2*tg;
                float4 c = acc[nt];
                float* p0 = sS + i0*SST + hf*128 + j0;
                float* p1 = p0 + 8*SST;
                if (hf == 0) {
                    p0[0] = (j0   == i0  ) ? -INFINITY : c.x*scale;
                    p0[1] = (j0+1 == i0  ) ? -INFINITY : c.y*scale;
                    p1[0] = (j0   == i0+8) ? -INFINITY : c.z*scale;
                    p1[1] = (j0+1 == i0+8) ? -INFINITY : c.w*scale;
                } else {
                    p0[0] = c.x*scale; p0[1] = c.y*scale;
                    p1[0] = c.z*scale; p1[1] = c.w*scale;
                }
            }
        }
    }
    __syncthreads();

    // V^T gather (reuses Q/K smem) + softmax (512 threads: quarter-row each)
    for (int p = tid; p < 256*16; p += 512) {
        int j = p >> 4, dc = (p & 15) * 4;
        int s = idxp[(size_t)((base + j) & (SS-1))*HH];
        float4 vv = *(const float4*)(vp + (size_t)s*DD + dc);
        sVT[(dc+0)*VST + j] = tf32r(vv.x);
        sVT[(dc+1)*VST + j] = tf32r(vv.y);
        sVT[(dc+2)*VST + j] = tf32r(vv.z);
        sVT[(dc+3)*VST + j] = tf32r(vv.w);
    }
    {
        int row = tid >> 2, q = tid & 3;
        float* rp = sS + row*SST + q*64;
        float mx = -INFINITY;
        #pragma unroll 4
        for (int c = 0; c < 16; c++) {
            float4 v = ((float4*)rp)[c];
            mx = fmaxf(mx, fmaxf(fmaxf(v.x,v.y), fmaxf(v.z,v.w)));
        }
        mx = fmaxf(mx, __shfl_xor_sync(0xffffffffu, mx, 1));
        mx = fmaxf(mx, __shfl_xor_sync(0xffffffffu, mx, 2));
        float sum = 0.f;
        #pragma unroll 4
        for (int c = 0; c < 16; c++) {
            float4 v = ((float4*)rp)[c];
            v.x = __expf(v.x - mx); v.y = __expf(v.y - mx);
            v.z = __expf(v.z - mx); v.w = __expf(v.w - mx);
            sum += (v.x + v.y) + (v.z + v.w);
            ((float4*)rp)[c] = v;
        }
        sum += __shfl_xor_sync(0xffffffffu, sum, 1);
        sum += __shfl_xor_sync(0xffffffffu, sum, 2);
        float inv = 1.f / sum;
        #pragma unroll 4
        for (int c = 0; c < 16; c++) {
            float4 v = ((float4*)rp)[c];
            v.x = tf32r(v.x*inv); v.y = tf32r(v.y*inv);
            v.z = tf32r(v.z*inv); v.w = tf32r(v.w*inv);
            ((float4*)rp)[c] = v;
        }
    }
    __syncthreads();

    // PV: out[128x64] = P[128x256] @ V^T, warp tile 16x32
    float4 o[4];
    #pragma unroll
    for (int j = 0; j < 4; j++) o[j] = make_float4(0.f,0.f,0.f,0.f);

    #pragma unroll 4
    for (int ks = 0; ks < 32; ks++) {
        int kc = ks * 8;
        uint32_t a[4], bfr[4][2];
        a[0] = __float_as_uint(sS[(warp_m+g  )*SST + kc+tg  ]);
        a[1] = __float_as_uint(sS[(warp_m+g+8)*SST + kc+tg  ]);
        a[2] = __float_as_uint(sS[(warp_m+g  )*SST + kc+tg+4]);
        a[3] = __float_as_uint(sS[(warp_m+g+8)*SST + kc+tg+4]);
        #pragma unroll
        for (int nt = 0; nt < 4; nt++) {
            int n0 = warp_nV + nt*8;
            bfr[nt][0] = __float_as_uint(sVT[(n0+g)*VST + kc+tg  ]);
            bfr[nt][1] = __float_as_uint(sVT[(n0+g)*VST + kc+tg+4]);
        }
        #pragma unroll
        for (int nt = 0; nt < 4; nt++)
            mma_tf32(o[nt], a[0],a[1],a[2],a[3], bfr[nt][0], bfr[nt][1]);
    }

    float* outp = g_outs + (size_t)b*SS*DD + h*DH;
    {
        int i0 = warp_m + g;
        int t0 = base + i0;
        #pragma unroll
        for (int nt = 0; nt < 4; nt++) {
            int d0 = warp_nV + nt*8 + 2*tg;
            float4 c = o[nt];
            *(float2*)(outp + (size_t)t0*DD + d0)     = make_float2(c.x, c.y);
            *(float2*)(outp + (size_t)(t0+8)*DD + d0) = make_float2(c.z, c.w);
            if (d0 == 0) {
                g_ch0[((size_t)b*SS + t0  )*HH + h] = c.x;
                g_ch0[((size_t)b*SS + t0+8)*HH + h] = c.z;
            }
        }
    }
}

// ---------------- 5) feature-0-only inverse scatter ----------------
__global__ void __launch_bounds__(256) scatter_kernel() {
    int i = blockIdx.x*256 + threadIdx.x;
    if (i >= BB*SS*HH) return;
    int h = i % HH;
    int b = i / (SS*HH);
    int p = g_idx[i];
    g_outs[((size_t)b*SS + p)*DD + h*DH] = g_ch0[i];
}

// ---------------- launch ----------------
extern "C" void kernel_launch(void* const* d_in, const int* in_sizes, int n_in,
                              void* d_out, int out_size) {
    const float* x  = (const float*)d_in[0];
    const float* Wh = (const float*)d_in[1];
    const float* Wq = (const float*)d_in[2];
    const float* bq = (const float*)d_in[3];
    const float* Wv = (const float*)d_in[4];
    const float* bv = (const float*)d_in[5];
    const float* Wo = (const float*)d_in[6];
    const float* bo = (const float*)d_in[7];
    float* out = (float*)d_out;

    float* qkp; cudaGetSymbolAddress((void**)&qkp, g_qk);
    float* vp;  cudaGetSymbolAddress((void**)&vp,  g_v);
    float* osp; cudaGetSymbolAddress((void**)&osp, g_outs);

    const int M = BB*SS;

    hash_kernel<<<M/32, dim3(32,32)>>>(x, Wh);
    sort_kernel<<<BB*HH, 1024>>>();

    size_t gsmem = (size_t)(2*128*AST + 2*256*AST) * sizeof(float);
    cudaFuncSetAttribute(gemm2, cudaFuncAttributeMaxDynamicSharedMemorySize, (int)gsmem);
    gemm2<<<dim3(8, M/128), 256, gsmem>>>(x, Wq, bq, qkp, Wv, bv, vp, 4, DD, DD);

    size_t asmem = (size_t)(128*SST + 2*128*QST) * sizeof(float);
    cudaFuncSetAttribute(attn_kernel, cudaFuncAttributeMaxDynamicSharedMemorySize, (int)asmem);
    dim3 ag(NB, HH, BB);
    attn_kernel<<<ag, 512, asmem>>>();

    scatter_kernel<<<(BB*SS*HH + 255)/256, 256>>>();
    gemm2<<<dim3(4, M/128), 256, gsmem>>>(osp, Wo, bo, out, Wo, bo, out, 4, DD, DD);
}

// round 9
// speedup vs baseline: 4.0042x; 1.1455x over previous
#include <cuda_runtime.h>
#include <math.h>
#include <stdint.h>

#define BB 4
#define SS 4096
#define DD 1024
#define HH 16
#define DH 64
#define BSZ 128
#define NB 32
#define EPSF 1e-4f

// ---------------- scratch ----------------
__device__ float g_angles[BB*SS*HH];
__device__ int   g_idx[BB*SS*HH];
__device__ int   g_inv[BB*SS*HH];
__device__ float g_qk[(size_t)BB*SS*DD];    // SORTED per head: [b, pos, h, d]
__device__ float g_v [(size_t)BB*SS*DD];    // SORTED per head
__device__ float g_outs[(size_t)BB*SS*DD];
__device__ float g_ch0[BB*SS*HH];

__device__ __forceinline__ float tf32r(float x) {
    uint32_t u;
    asm("cvt.rna.tf32.f32 %0, %1;" : "=r"(u) : "f"(x));
    return __uint_as_float(u);
}
__device__ __forceinline__ uint32_t tf32u(float x) {
    uint32_t u;
    asm("cvt.rna.tf32.f32 %0, %1;" : "=r"(u) : "f"(x));
    return u;
}

__device__ __forceinline__ void mma_tf32(float4& d,
                                         uint32_t a0, uint32_t a1, uint32_t a2, uint32_t a3,
                                         uint32_t b0, uint32_t b1) {
    asm volatile(
        "mma.sync.aligned.m16n8k8.row.col.f32.tf32.tf32.f32 "
        "{%0,%1,%2,%3},{%4,%5,%6,%7},{%8,%9},{%0,%1,%2,%3};"
        : "+f"(d.x), "+f"(d.y), "+f"(d.z), "+f"(d.w)
        : "r"(a0), "r"(a1), "r"(a2), "r"(a3), "r"(b0), "r"(b1));
}

__device__ __forceinline__ void cpa16(uint32_t saddr, const float* g) {
    asm volatile("cp.async.cg.shared.global [%0], [%1], 16;\n" :: "r"(saddr), "l"(g));
}

// ---------------- 1) hash (exact fp32 serial chain, matches ref) ----------------
__global__ void __launch_bounds__(1024) hash_kernel(const float* __restrict__ x,
                                                    const float* __restrict__ Wh) {
    __shared__ float xs[32][257];
    __shared__ float hs[32][34];
    int g = threadIdx.x;
    int o = threadIdx.y;
    int tid = o * 32 + g;
    int tok0 = blockIdx.x * 32;
    const float* xbase = x + (size_t)tok0 * DD;
    float acc = 0.f;
    for (int c = 0; c < 4; c++) {
        __syncthreads();
        for (int i = tid; i < 32*64; i += 1024) {
            int r = i >> 6, cc = i & 63;
            float4 v = *(const float4*)(xbase + (size_t)r*DD + c*256 + cc*4);
            float* dst = &xs[r][cc*4];
            dst[0]=v.x; dst[1]=v.y; dst[2]=v.z; dst[3]=v.w;
        }
        __syncthreads();
        const float* w = Wh + (size_t)o*DD + c*256;
        #pragma unroll 8
        for (int k = 0; k < 256; k++)
            acc = fmaf(xs[g][k], __ldg(w + k), acc);
    }
    hs[g][o] = acc;
    __syncthreads();
    if (o < HH) {
        float h0 = hs[g][2*o], h1 = hs[g][2*o+1];
        g_angles[((size_t)(tok0 + g))*HH + o] = __fdiv_rn(h0, h1 + EPSF);
    }
}

// ---------------- 2) STABLE bitonic argsort + inverse ----------------
__global__ void __launch_bounds__(1024) sort_kernel() {
    int b = blockIdx.x / HH, h = blockIdx.x % HH;
    __shared__ float key[SS];
    __shared__ int   val[SS];
    int tid = threadIdx.x;
    for (int i = tid; i < SS; i += 1024) {
        key[i] = g_angles[((size_t)b*SS + i)*HH + h];
        val[i] = i;
    }
    __syncthreads();
    for (int k = 2; k <= SS; k <<= 1) {
        for (int j = k >> 1; j > 0; j >>= 1) {
            for (int i = tid; i < SS; i += 1024) {
                int ixj = i ^ j;
                if (ixj > i) {
                    bool up = ((i & k) == 0);
                    float ki = key[i], kj = key[ixj];
                    int   vi = val[i], vj = val[ixj];
                    bool gt = (ki > kj) || (ki == kj && vi > vj);
                    if (gt == up) {
                        key[i] = kj; key[ixj] = ki;
                        val[i] = vj; val[ixj] = vi;
                    }
                }
            }
            __syncthreads();
        }
    }
    for (int i = tid; i < SS; i += 1024) {
        int v = val[i];
        g_idx[((size_t)b*SS + i)*HH + h] = v;
        g_inv[((size_t)b*SS + v)*HH + h] = i;
    }
}

// ---------------- 3) TF32 GEMM v3: 128x128x32, 2-stage cp.async, 2 blocks/SM ----
#define AST 36

__global__ void __launch_bounds__(256, 2) gemm3(const float* __restrict__ A,
                                                const float* __restrict__ W0,
                                                const float* __restrict__ b0,
                                                float* __restrict__ C0,
                                                const float* __restrict__ W1,
                                                const float* __restrict__ b1,
                                                float* __restrict__ C1,
                                                int split, int N, int K, int mode) {
    extern __shared__ float smem[];
    float* As = smem;                        // [2][128][AST]
    float* Bs = smem + 2*128*AST;            // [2][128][AST]

    const float* W; const float* bias; float* C;
    int bx = blockIdx.x;
    if (bx < split) { W = W0; bias = b0; C = C0; }
    else            { W = W1; bias = b1; C = C1; bx -= split; }
    int bm = blockIdx.y * 128, bn = bx * 128;

    int tid  = threadIdx.x;
    int lane = tid & 31, wid = tid >> 5;
    int g = lane >> 2, tg = lane & 3;
    int warp_m = (wid & 1) * 64;             // 0,64
    int warp_n = (wid >> 1) * 32;            // 0,32,64,96

    float4 acc[4][4];
    #pragma unroll
    for (int i = 0; i < 4; i++)
        #pragma unroll
        for (int j = 0; j < 4; j++) acc[i][j] = make_float4(0.f,0.f,0.f,0.f);

    auto load_tile = [&](int k0, int buf) {
        uint32_t abase = (uint32_t)__cvta_generic_to_shared(As + buf*128*AST);
        uint32_t bbase = (uint32_t)__cvta_generic_to_shared(Bs + buf*128*AST);
        #pragma unroll
        for (int i = 0; i < 4; i++) {
            int idx = tid + i*256;
            int r = idx >> 3, c4 = (idx & 7) * 4;
            cpa16(abase + (r*AST + c4)*4, A + (size_t)(bm + r)*K + k0 + c4);
            cpa16(bbase + (r*AST + c4)*4, W + (size_t)(bn + r)*K + k0 + c4);
        }
        asm volatile("cp.async.commit_group;\n");
    };

    load_tile(0, 0);

    int nkt = K / 32;
    for (int kt = 0; kt < nkt; kt++) {
        int cur = kt & 1;
        if (kt + 1 < nkt) {
            load_tile((kt + 1) * 32, (kt + 1) & 1);
            asm volatile("cp.async.wait_group 1;\n");
        } else {
            asm volatile("cp.async.wait_group 0;\n");
        }
        __syncthreads();

        const float* Ab = As + cur*128*AST;
        const float* Bb = Bs + cur*128*AST;
        #pragma unroll
        for (int ks = 0; ks < 4; ks++) {
            int kc = ks * 8;
            uint32_t a[4][4], b[4][2];
            #pragma unroll
            for (int mt = 0; mt < 4; mt++) {
                int r0 = warp_m + mt*16;
                a[mt][0] = tf32u(Ab[(r0+g  )*AST + kc+tg  ]);
                a[mt][1] = tf32u(Ab[(r0+g+8)*AST + kc+tg  ]);
                a[mt][2] = tf32u(Ab[(r0+g  )*AST + kc+tg+4]);
                a[mt][3] = tf32u(Ab[(r0+g+8)*AST + kc+tg+4]);
            }
            #pragma unroll
            for (int nt = 0; nt < 4; nt++) {
                int n0 = warp_n + nt*8;
                b[nt][0] = tf32u(Bb[(n0+g)*AST + kc+tg  ]);
                b[nt][1] = tf32u(Bb[(n0+g)*AST + kc+tg+4]);
            }
            #pragma unroll
            for (int mt = 0; mt < 4; mt++)
                #pragma unroll
                for (int nt = 0; nt < 4; nt++)
                    mma_tf32(acc[mt][nt], a[mt][0],a[mt][1],a[mt][2],a[mt][3],
                             b[nt][0], b[nt][1]);
        }
        __syncthreads();
    }

    if (mode == 0) {
        #pragma unroll
        for (int mt = 0; mt < 4; mt++) {
            int r0 = bm + warp_m + mt*16 + g;
            #pragma unroll
            for (int nt = 0; nt < 4; nt++) {
                int col = bn + warp_n + nt*8 + 2*tg;
                float bx2 = __ldg(bias + col), by = __ldg(bias + col + 1);
                float4 c = acc[mt][nt];
                *(float2*)(C + (size_t)r0*N + col)     = make_float2(c.x + bx2, c.y + by);
                *(float2*)(C + (size_t)(r0+8)*N + col) = make_float2(c.z + bx2, c.w + by);
            }
        }
    } else {
        // scatter rows into per-head sorted order via inverse permutation
        int hsel = (bn + warp_n) >> 6;   // 32-col warp span stays inside one head
        #pragma unroll
        for (int mt = 0; mt < 4; mt++) {
            int r0 = bm + warp_m + mt*16 + g;
            int r1 = r0 + 8;
            int p0 = g_inv[(size_t)r0*HH + hsel];
            int p1 = g_inv[(size_t)r1*HH + hsel];
            size_t o0 = ((size_t)(r0 & ~(SS-1)) + p0) * (size_t)N;
            size_t o1 = ((size_t)(r1 & ~(SS-1)) + p1) * (size_t)N;
            #pragma unroll
            for (int nt = 0; nt < 4; nt++) {
                int col = bn + warp_n + nt*8 + 2*tg;
                float bx2 = __ldg(bias + col), by = __ldg(bias + col + 1);
                float4 c = acc[mt][nt];
                *(float2*)(C + o0 + col) = make_float2(c.x + bx2, c.y + by);
                *(float2*)(C + o1 + col) = make_float2(c.z + bx2, c.w + by);
            }
        }
    }
}

// ---------------- 4) attention: sorted inputs, cp.async, 512 threads ----------------
#define SST 260
#define QST 68
#define VST 72   // 8*tg+g bank pattern -> conflict-free PV B-frags

__global__ void __launch_bounds__(512) attn_kernel() {
    extern __shared__ float smem[];
    float* sS = smem;                    // 128 x SST
    float* sQ = smem + 128*SST;          // 128 x QST
    float* sK = sQ + 128*QST;            // 128 x QST
    float* sV = sQ;                      // 256 x VST (reuses Q/K + 4KB tail)

    int tid = threadIdx.x;
    int lane = tid & 31, wid = tid >> 5;
    int g = lane >> 2, tg = lane & 3;
    int warp_m  = (wid & 7) * 16;
    int warp_nS = (wid >> 3) * 64;
    int warp_nV = (wid >> 3) * 32;

    int n = blockIdx.x, h = blockIdx.y, b = blockIdx.z;
    int base = n * BSZ;
    const float* qkp = g_qk + (size_t)b*SS*DD + h*DH;   // sorted rows
    const float* vp  = g_v  + (size_t)b*SS*DD + h*DH;
    const float scale = 0.03125f;

    uint32_t sqb = (uint32_t)__cvta_generic_to_shared(sQ);
    uint32_t skb = (uint32_t)__cvta_generic_to_shared(sK);
    uint32_t svb = (uint32_t)__cvta_generic_to_shared(sV);

    // Q + K half0 (contiguous sorted rows)
    for (int p = tid; p < 128*16; p += 512) {
        int r = p >> 4, seg = p & 15;
        cpa16(sqb + (r*QST + seg*4)*4, qkp + (size_t)(base + r)*DD + seg*4);
    }
    for (int p = tid; p < 128*16; p += 512) {
        int r = p >> 4, seg = p & 15;
        cpa16(skb + (r*QST + seg*4)*4, qkp + (size_t)((base + r) & (SS-1))*DD + seg*4);
    }
    asm volatile("cp.async.commit_group;\n");
    asm volatile("cp.async.wait_group 0;\n");
    __syncthreads();

    #pragma unroll 1
    for (int hf = 0; hf < 2; hf++) {
        if (hf == 1) {
            __syncthreads();   // all done reading K half0
            for (int p = tid; p < 128*16; p += 512) {
                int r = p >> 4, seg = p & 15;
                cpa16(skb + (r*QST + seg*4)*4,
                      qkp + (size_t)((base + 128 + r) & (SS-1))*DD + seg*4);
            }
            asm volatile("cp.async.commit_group;\n");
            asm volatile("cp.async.wait_group 0;\n");
            __syncthreads();
        }
        float4 acc[8];
        #pragma unroll
        for (int j = 0; j < 8; j++) acc[j] = make_float4(0.f,0.f,0.f,0.f);

        #pragma unroll
        for (int ks = 0; ks < 8; ks++) {
            int kc = ks * 8;
            uint32_t a[4], bfr[8][2];
            a[0] = tf32u(sQ[(warp_m+g  )*QST + kc+tg  ]);
            a[1] = tf32u(sQ[(warp_m+g+8)*QST + kc+tg  ]);
            a[2] = tf32u(sQ[(warp_m+g  )*QST + kc+tg+4]);
            a[3] = tf32u(sQ[(warp_m+g+8)*QST + kc+tg+4]);
            #pragma unroll
            for (int nt = 0; nt < 8; nt++) {
                int n0 = warp_nS + nt*8;
                bfr[nt][0] = tf32u(sK[(n0+g)*QST + kc+tg  ]);
                bfr[nt][1] = tf32u(sK[(n0+g)*QST + kc+tg+4]);
            }
            #pragma unroll
            for (int nt = 0; nt < 8; nt++)
                mma_tf32(acc[nt], a[0],a[1],a[2],a[3], bfr[nt][0], bfr[nt][1]);
        }
        {
            int i0 = warp_m + g;
            #pragma unroll
            for (int nt = 0; nt < 8; nt++) {
                int j0 = warp_nS + nt*8 + 2*tg;
                float4 c = acc[nt];
                float* p0 = sS + i0*SST + hf*128 + j0;
                float* p1 = p0 + 8*SST;
                if (hf == 0) {
                    p0[0] = (j0   == i0  ) ? -INFINITY : c.x*scale;
                    p0[1] = (j0+1 == i0  ) ? -INFINITY : c.y*scale;
                    p1[0] = (j0   == i0+8) ? -INFINITY : c.z*scale;
                    p1[1] = (j0+1 == i0+8) ? -INFINITY : c.w*scale;
                } else {
                    p0[0] = c.x*scale; p0[1] = c.y*scale;
                    p1[0] = c.z*scale; p1[1] = c.w*scale;
                }
            }
        }
    }
    __syncthreads();   // scores in sS; sQ/sK free

    // V load (overlaps softmax)
    for (int p = tid; p < 256*16; p += 512) {
        int j = p >> 4, seg = p & 15;
        cpa16(svb + (j*VST + seg*4)*4, vp + (size_t)((base + j) & (SS-1))*DD + seg*4);
    }
    asm volatile("cp.async.commit_group;\n");

    // softmax (quarter-row per thread)
    {
        int row = tid >> 2, q = tid & 3;
        float* rp = sS + row*SST + q*64;
        float mx = -INFINITY;
        #pragma unroll 4
        for (int c = 0; c < 16; c++) {
            float4 v = ((float4*)rp)[c];
            mx = fmaxf(mx, fmaxf(fmaxf(v.x,v.y), fmaxf(v.z,v.w)));
        }
        mx = fmaxf(mx, __shfl_xor_sync(0xffffffffu, mx, 1));
        mx = fmaxf(mx, __shfl_xor_sync(0xffffffffu, mx, 2));
        float sum = 0.f;
        #pragma unroll 4
        for (int c = 0; c < 16; c++) {
            float4 v = ((float4*)rp)[c];
            v.x = __expf(v.x - mx); v.y = __expf(v.y - mx);
            v.z = __expf(v.z - mx); v.w = __expf(v.w - mx);
            sum += (v.x + v.y) + (v.z + v.w);
            ((float4*)rp)[c] = v;
        }
        sum += __shfl_xor_sync(0xffffffffu, sum, 1);
        sum += __shfl_xor_sync(0xffffffffu, sum, 2);
        float inv = 1.f / sum;
        #pragma unroll 4
        for (int c = 0; c < 16; c++) {
            float4 v = ((float4*)rp)[c];
            v.x = tf32r(v.x*inv); v.y = tf32r(v.y*inv);
            v.z = tf32r(v.z*inv); v.w = tf32r(v.w*inv);
            ((float4*)rp)[c] = v;
        }
    }
    asm volatile("cp.async.wait_group 0;\n");
    __syncthreads();

    // PV: out[128x64] = P[128x256] @ V[256x64] (V is k-major: natural B operand)
    float4 o[4];
    #pragma unroll
    for (int j = 0; j < 4; j++) o[j] = make_float4(0.f,0.f,0.f,0.f);

    #pragma unroll 4
    for (int ks = 0; ks < 32; ks++) {
        int kc = ks * 8;
        uint32_t a[4], bfr[4][2];
        a[0] = __float_as_uint(sS[(warp_m+g  )*SST + kc+tg  ]);
        a[1] = __float_as_uint(sS[(warp_m+g+8)*SST + kc+tg  ]);
        a[2] = __float_as_uint(sS[(warp_m+g  )*SST + kc+tg+4]);
        a[3] = __float_as_uint(sS[(warp_m+g+8)*SST + kc+tg+4]);
        #pragma unroll
        for (int nt = 0; nt < 4; nt++) {
            int n0 = warp_nV + nt*8;
            bfr[nt][0] = tf32u(sV[(kc+tg  )*VST + n0+g]);
            bfr[nt][1] = tf32u(sV[(kc+tg+4)*VST + n0+g]);
        }
        #pragma unroll
        for (int nt = 0; nt < 4; nt++)
            mma_tf32(o[nt], a[0],a[1],a[2],a[3], bfr[nt][0], bfr[nt][1]);
    }

    float* outp = g_outs + (size_t)b*SS*DD + h*DH;
    {
        int i0 = warp_m + g;
        int t0 = base + i0;
        #pragma unroll
        for (int nt = 0; nt < 4; nt++) {
            int d0 = warp_nV + nt*8 + 2*tg;
            float4 c = o[nt];
            *(float2*)(outp + (size_t)t0*DD + d0)     = make_float2(c.x, c.y);
            *(float2*)(outp + (size_t)(t0+8)*DD + d0) = make_float2(c.z, c.w);
            if (d0 == 0) {
                g_ch0[((size_t)b*SS + t0  )*HH + h] = c.x;
                g_ch0[((size_t)b*SS + t0+8)*HH + h] = c.z;
            }
        }
    }
}

// ---------------- 5) feature-0-only inverse scatter ----------------
__global__ void __launch_bounds__(256) scatter_kernel() {
    int i = blockIdx.x*256 + threadIdx.x;
    if (i >= BB*SS*HH) return;
    int h = i % HH;
    int b = i / (SS*HH);
    int p = g_idx[i];
    g_outs[((size_t)b*SS + p)*DD + h*DH] = g_ch0[i];
}

// ---------------- launch ----------------
extern "C" void kernel_launch(void* const* d_in, const int* in_sizes, int n_in,
                              void* d_out, int out_size) {
    const float* x  = (const float*)d_in[0];
    const float* Wh = (const float*)d_in[1];
    const float* Wq = (const float*)d_in[2];
    const float* bq = (const float*)d_in[3];
    const float* Wv = (const float*)d_in[4];
    const float* bv = (const float*)d_in[5];
    const float* Wo = (const float*)d_in[6];
    const float* bo = (const float*)d_in[7];
    float* out = (float*)d_out;

    float* qkp; cudaGetSymbolAddress((void**)&qkp, g_qk);
    float* vp;  cudaGetSymbolAddress((void**)&vp,  g_v);
    float* osp; cudaGetSymbolAddress((void**)&osp, g_outs);

    const int M = BB*SS;

    hash_kernel<<<M/32, dim3(32,32)>>>(x, Wh);
    sort_kernel<<<BB*HH, 1024>>>();

    size_t gsmem = (size_t)(4*128*AST) * sizeof(float);   // 73,728 B (2 stages A+B)
    cudaFuncSetAttribute(gemm3, cudaFuncAttributeMaxDynamicSharedMemorySize, (int)gsmem);
    // fused Q/V projection, rows scattered into per-head sorted order
    gemm3<<<dim3(16, M/128), 256, gsmem>>>(x, Wq, bq, qkp, Wv, bv, vp, 8, DD, DD, 1);

    size_t asmem = (size_t)(128*SST + 2*128*QST + 1024) * sizeof(float);  // 206,848 B
    cudaFuncSetAttribute(attn_kernel, cudaFuncAttributeMaxDynamicSharedMemorySize, (int)asmem);
    dim3 ag(NB, HH, BB);
    attn_kernel<<<ag, 512, asmem>>>();

    scatter_kernel<<<(BB*SS*HH + 255)/256, 256>>>();
    gemm3<<<dim3(8, M/128), 256, gsmem>>>(osp, Wo, bo, out, Wo, bo, out, 8, DD, DD, 0);
}